// round 8
// baseline (speedup 1.0000x reference)
#include <cuda_runtime.h>
#include <math.h>

typedef unsigned long long u64t;

// Packed f32x2 FMA (Blackwell packed fp32 path)
#define FMA2(d, a, b) asm("fma.rn.f32x2 %0, %1, %2, %0;" : "+l"(d) : "l"(a), "l"(b))
#define PACKF2(o, lo, hi) asm("mov.b64 %0, {%1, %2};" : "=l"(o) : "r"(__float_as_uint(lo)), "r"(__float_as_uint(hi)))

// Scratch (allocation-free rule: __device__ globals)
__device__ float g_s2[4096 * 64 * 49];    // pooled conv2 output (N,64,7,7)
__device__ float g_fc1[4096 * 128];       // fc1 output (post relu)
__device__ float g_w2eff[64 * 153];       // conv2 effective weights: [o][17*9] stride 153

// ---------------------------------------------------------------------------
// prep: fold the 16 identical identity channels of conv1 into ONE conv2
// input channel: w_eff[o][144+k] = sum_{ci=16..31} w2[o][ci][k]
// ---------------------------------------------------------------------------
__global__ void pcf_prep(const float* __restrict__ w2g)
{
    int idx = blockIdx.x * 256 + threadIdx.x;
    if (idx >= 64 * 153) return;
    int o = idx / 153, k = idx - o * 153;
    float v;
    if (k < 144) {
        v = w2g[o * 288 + k];                 // gabor ci 0..15 verbatim
    } else {
        int kk = k - 144;                     // 0..8
        v = 0.f;
#pragma unroll
        for (int ci = 16; ci < 32; ci++) v += w2g[o * 288 + ci * 9 + kk];
    }
    g_w2eff[o * 153 + k] = v;
}

// ---------------------------------------------------------------------------
// k2f: FUSED conv1(gabor+identity)+relu+pool -> conv2(17ch eff)+bias+relu+pool
// Persistent over 4 images per block, grid 1024, 448 threads.
// Weights pre-splatted (w,w) u64 in smem; x register-prefetched across images.
// ---------------------------------------------------------------------------
__global__ void __launch_bounds__(448, 1) pcf_k2f(
    const float* __restrict__ x, const float* __restrict__ theta,
    const float* __restrict__ sigma, const float* __restrict__ gamma_,
    const float* __restrict__ lambd, const float* __restrict__ psi,
    const float* __restrict__ b2)
{
    extern __shared__ char smraw[];
    u64t*  wsu = (u64t*)smraw;                      // [64][154] splat weights
    float* si  = (float*)(smraw + 64 * 154 * 8);    // 17ch x 16x16 padded = 4352
    float* ps  = si + 4352;                          // 30x30 padded image = 900
    float* gw  = ps + 900;                           // 16x9 gabor filters

    const int t = threadIdx.x;
    const int n_base = blockIdx.x * 4;

    // ---- one-time prologue ----
    for (int idx = t; idx < 4352; idx += 448) si[idx] = 0.f;
    for (int idx = t; idx < 900; idx += 448) ps[idx] = 0.f;
    for (int idx = t; idx < 9792; idx += 448) {
        int o = idx / 153, k = idx - o * 153;
        float w = g_w2eff[idx];
        u64t sp; PACKF2(sp, w, w);
        wsu[o * 154 + k] = sp;
    }
    if (t < 144) {
        int f = t / 9, k = t - f * 9;
        float xg = (float)(k / 3) - 1.f;
        float yg = (float)(k % 3) - 1.f;
        float th = theta[f];
        float cth = cosf(th), sth = sinf(th);
        float xt = xg * cth + yg * sth;
        float yt = -xg * sth + yg * cth;
        float sx = sigma[f];
        float sy = sigma[f] / gamma_[f];
        float env = expf(-0.5f * (xt * xt / (sx * sx) + yt * yt / (sy * sy)));
        float car = cosf(6.283185307179586f * xt / lambd[f] + psi[f]);
        gw[f * 9 + k] = env * car;
    }
    // prefetch x for image 0
    float rx0, rx1;
    {
        const float* xim = x + (size_t)n_base * 784;
        rx0 = (t < 784) ? xim[t] : 0.f;
        rx1 = (t + 448 < 784) ? xim[t + 448] : 0.f;
    }
    __syncthreads();

    const int warp = t >> 5, lane = t & 31;
    const int i = warp >> 1;                    // pooled row 0..6
    const int o = ((warp & 1) << 5) | lane;     // output channel 0..63
    const u64t* wsrow = wsu + o * 154;
    const float* rowbase = si + 2 * i * 16;
    const float bbias = b2[o];

    for (int m = 0; m < 4; m++) {
        // ---- stage image into padded ps ----
        if (t < 784)       ps[(t / 28 + 1) * 30 + (t % 28 + 1)] = rx0;
        if (t + 448 < 784) ps[((t + 448) / 28 + 1) * 30 + ((t + 448) % 28 + 1)] = rx1;
        __syncthreads();

        // prefetch next image's pixels (latency hidden behind conv work)
        float rn0 = 0.f, rn1 = 0.f;
        if (m < 3) {
            const float* xim = x + (size_t)(n_base + m + 1) * 784;
            rn0 = (t < 784) ? xim[t] : 0.f;
            rn1 = (t + 448 < 784) ? xim[t + 448] : 0.f;
        }

        // ---- conv1 + relu + maxpool -> si interior ----
        for (int idx = t; idx < 3332; idx += 448) {
            int ci = idx / 196, p = idx - ci * 196;
            int pi = p / 14, pj = p - pi * 14;
            float v;
            if (ci == 16) {
                float mx = fmaxf(fmaxf(ps[(2 * pi + 1) * 30 + 2 * pj + 1],
                                       ps[(2 * pi + 1) * 30 + 2 * pj + 2]),
                                 fmaxf(ps[(2 * pi + 2) * 30 + 2 * pj + 1],
                                       ps[(2 * pi + 2) * 30 + 2 * pj + 2]));
                v = fmaxf(mx, 0.f);
            } else {
                float w[9];
#pragma unroll
                for (int k = 0; k < 9; k++) w[k] = gw[ci * 9 + k];
                float mx = -1e30f;
#pragma unroll
                for (int di = 0; di < 2; di++)
#pragma unroll
                    for (int dj = 0; dj < 2; dj++) {
                        float s = 0.f;
#pragma unroll
                        for (int kh = 0; kh < 3; kh++)
#pragma unroll
                            for (int kw = 0; kw < 3; kw++)
                                s += ps[(2 * pi + di + kh) * 30 + (2 * pj + dj + kw)] * w[kh * 3 + kw];
                        mx = fmaxf(mx, s);
                    }
                v = fmaxf(mx, 0.f);
            }
            si[ci * 256 + (pi + 1) * 16 + (pj + 1)] = v;
        }
        __syncthreads();

        // ---- conv2 over 17 channels + bias + relu + pool ----
        u64t acc2[2][7];
#pragma unroll
        for (int lr = 0; lr < 2; lr++)
#pragma unroll
            for (int j = 0; j < 7; j++) acc2[lr][j] = 0ull;

#pragma unroll 1
        for (int ci = 0; ci < 17; ci++) {
            u64t wp[9];
#pragma unroll
            for (int k = 0; k < 9; k++) wp[k] = wsrow[ci * 9 + k];
            const float* rb = rowbase + ci * 256;
#pragma unroll
            for (int r = 0; r < 4; r++) {
                float rv[16];
                const float4* rp = (const float4*)(rb + r * 16);
#pragma unroll
                for (int q = 0; q < 4; q++) {
                    float4 v = rp[q];
                    rv[4 * q] = v.x; rv[4 * q + 1] = v.y; rv[4 * q + 2] = v.z; rv[4 * q + 3] = v.w;
                }
                u64t p0[8], p1[7];
#pragma unroll
                for (int q = 0; q < 8; q++) PACKF2(p0[q], rv[2 * q], rv[2 * q + 1]);
#pragma unroll
                for (int q = 0; q < 7; q++) PACKF2(p1[q], rv[2 * q + 1], rv[2 * q + 2]);
#pragma unroll
                for (int lr = 0; lr < 2; lr++) {
                    const int kh = r - lr;
                    if (kh >= 0 && kh < 3) {
                        u64t w0 = wp[kh * 3], w1 = wp[kh * 3 + 1], w2v = wp[kh * 3 + 2];
#pragma unroll
                        for (int j = 0; j < 7; j++) {
                            FMA2(acc2[lr][j], p0[j], w0);
                            FMA2(acc2[lr][j], p1[j], w1);
                            FMA2(acc2[lr][j], p0[j + 1], w2v);
                        }
                    }
                }
            }
        }

        float* outp = g_s2 + (size_t)(n_base + m) * 3136 + o * 49 + i * 7;
#pragma unroll
        for (int j = 0; j < 7; j++) {
            union { u64t u; float2 f; } a0, a1;
            a0.u = acc2[0][j];
            a1.u = acc2[1][j];
            float mx = fmaxf(fmaxf(a0.f.x, a0.f.y), fmaxf(a1.f.x, a1.f.y));
            outp[j] = fmaxf(mx + bbias, 0.f);
        }
        __syncthreads();   // si/ps reusable next iteration
        rx0 = rn0; rx1 = rn1;
    }
}

// ---------------------------------------------------------------------------
// k3: fc1 = relu(A(4096x3136) @ W^T(3136x128) + b) -> g_fc1
// 64x64x32 tiles, 256 threads. A stored pre-splatted as u64 (a,a) pairs with
// 16B-unit XOR swizzle; B adjacent cols read directly as f32x2. Inner loop:
// 3 LDS.128 + 8 FFMA2 per kk, zero packs. Register-double-buffered gmem loads.
// ---------------------------------------------------------------------------
__global__ void __launch_bounds__(256) pcf_k3(
    const float* __restrict__ w1, const float* __restrict__ b1)
{
    __shared__ u64t  As2u[32 * 64];   // splat pairs, swizzled
    __shared__ float Bs[32 * 64];     // float4-group swizzled
    const int t = threadIdx.x;
    const int tx = t & 15, ty = t >> 4;
    const int n0 = blockIdx.x * 64;
    const int m0 = blockIdx.y * 64;

    u64t acc2[4][2];
#pragma unroll
    for (int u = 0; u < 4; u++) { acc2[u][0] = 0ull; acc2[u][1] = 0ull; }

    float ra[8], rbv[8];
    // load kt=0
#pragma unroll
    for (int s = 0; s < 8; s++) {
        int idx = t + s * 256;
        int k = idx & 31, row = idx >> 5;
        ra[s]  = g_s2[(size_t)(n0 + row) * 3136 + k];
        rbv[s] = w1[(size_t)(m0 + row) * 3136 + k];
    }
#pragma unroll
    for (int s = 0; s < 8; s++) {
        int idx = t + s * 256;
        int k = idx & 31, row = idx >> 5;
        u64t sp; PACKF2(sp, ra[s], ra[s]);
        As2u[k * 64 + ((((row >> 1) ^ k) << 1) | (row & 1))] = sp;
        Bs[k * 64 + ((((row >> 2) ^ (k & 15)) << 2) | (row & 3))] = rbv[s];
    }
    __syncthreads();

    for (int kt = 0; kt < 98; kt++) {
        if (kt < 97) {
#pragma unroll
            for (int s = 0; s < 8; s++) {
                int idx = t + s * 256;
                int k = idx & 31, row = idx >> 5;
                ra[s]  = g_s2[(size_t)(n0 + row) * 3136 + (kt + 1) * 32 + k];
                rbv[s] = w1[(size_t)(m0 + row) * 3136 + (kt + 1) * 32 + k];
            }
        }
#pragma unroll
        for (int kk = 0; kk < 32; kk++) {
            ulonglong2 bv = *(const ulonglong2*)(Bs + kk * 64 + ((tx ^ (kk & 15)) << 2));
            ulonglong2 a0 = *(const ulonglong2*)(As2u + kk * 64 + (((ty * 2) ^ kk) << 1));
            ulonglong2 a1 = *(const ulonglong2*)(As2u + kk * 64 + (((ty * 2 + 1) ^ kk) << 1));
            FMA2(acc2[0][0], bv.x, a0.x); FMA2(acc2[0][1], bv.y, a0.x);
            FMA2(acc2[1][0], bv.x, a0.y); FMA2(acc2[1][1], bv.y, a0.y);
            FMA2(acc2[2][0], bv.x, a1.x); FMA2(acc2[2][1], bv.y, a1.x);
            FMA2(acc2[3][0], bv.x, a1.y); FMA2(acc2[3][1], bv.y, a1.y);
        }
        __syncthreads();
        if (kt < 97) {
#pragma unroll
            for (int s = 0; s < 8; s++) {
                int idx = t + s * 256;
                int k = idx & 31, row = idx >> 5;
                u64t sp; PACKF2(sp, ra[s], ra[s]);
                As2u[k * 64 + ((((row >> 1) ^ k) << 1) | (row & 1))] = sp;
                Bs[k * 64 + ((((row >> 2) ^ (k & 15)) << 2) | (row & 3))] = rbv[s];
            }
            __syncthreads();
        }
    }

#pragma unroll
    for (int u = 0; u < 4; u++) {
        int nrow = n0 + ty * 4 + u;
#pragma unroll
        for (int p = 0; p < 2; p++) {
            union { u64t v; float2 f; } cv;
            cv.v = acc2[u][p];
            int mcol = m0 + tx * 4 + p * 2;
            g_fc1[(size_t)nrow * 128 + mcol]     = fmaxf(cv.f.x + b1[mcol], 0.f);
            g_fc1[(size_t)nrow * 128 + mcol + 1] = fmaxf(cv.f.y + b1[mcol + 1], 0.f);
        }
    }
}

// ---------------------------------------------------------------------------
// k4: fc2 = g_fc1 @ W2^T + b2 -> out (4096x10). 4 lanes/output + shfl reduce.
// ---------------------------------------------------------------------------
__global__ void __launch_bounds__(256) pcf_k4(
    const float* __restrict__ w2, const float* __restrict__ b2,
    float* __restrict__ out)
{
    int gid = blockIdx.x * 256 + threadIdx.x;   // 640*256 = 163840 = 40960*4
    int oi = gid >> 2, part = gid & 3;
    int nrow = oi / 10, o = oi - nrow * 10;
    const float4* a = (const float4*)(g_fc1 + (size_t)nrow * 128 + part * 32);
    const float4* w = (const float4*)(w2 + o * 128 + part * 32);
    float s = 0.f;
#pragma unroll
    for (int q = 0; q < 8; q++) {
        float4 av = a[q], wv = w[q];
        s += av.x * wv.x + av.y * wv.y + av.z * wv.z + av.w * wv.w;
    }
    s += __shfl_xor_sync(0xffffffffu, s, 1);
    s += __shfl_xor_sync(0xffffffffu, s, 2);
    if (part == 0) out[oi] = s + b2[o];
}

// ---------------------------------------------------------------------------
extern "C" void kernel_launch(void* const* d_in, const int* in_sizes, int n_in,
                              void* d_out, int out_size)
{
    const float* x       = (const float*)d_in[0];
    const float* theta   = (const float*)d_in[1];
    const float* sigma   = (const float*)d_in[2];
    const float* gamma_  = (const float*)d_in[3];
    const float* lambd   = (const float*)d_in[4];
    const float* psi     = (const float*)d_in[5];
    const float* conv2_w = (const float*)d_in[6];
    const float* conv2_b = (const float*)d_in[7];
    const float* fc1_w   = (const float*)d_in[8];
    const float* fc1_b   = (const float*)d_in[9];
    const float* fc2_w   = (const float*)d_in[10];
    const float* fc2_b   = (const float*)d_in[11];
    float* out = (float*)d_out;

    const int k2_smem = 64 * 154 * 8 + (4352 + 900 + 144) * 4;  // 100432 bytes
    cudaFuncSetAttribute(pcf_k2f, cudaFuncAttributeMaxDynamicSharedMemorySize, k2_smem);

    pcf_prep<<<39, 256>>>(conv2_w);
    pcf_k2f<<<1024, 448, k2_smem>>>(x, theta, sigma, gamma_, lambd, psi, conv2_b);
    pcf_k3<<<dim3(64, 2), 256>>>(fc1_w, fc1_b);
    pcf_k4<<<640, 256>>>(fc2_w, fc2_b, out);
}

// round 10
// speedup vs baseline: 1.7361x; 1.7361x over previous
#include <cuda_runtime.h>
#include <math.h>

typedef unsigned long long u64t;

// Packed f32x2 FMA (Blackwell packed fp32 path)
#define FMA2(d, a, b) asm("fma.rn.f32x2 %0, %1, %2, %0;" : "+l"(d) : "l"(a), "l"(b))
#define PACKF2(o, lo, hi) asm("mov.b64 %0, {%1, %2};" : "=l"(o) : "r"(__float_as_uint(lo)), "r"(__float_as_uint(hi)))

// Scratch (allocation-free rule: __device__ globals)
__device__ float g_s1[4096 * 17 * 196];   // pooled conv1 output (N,17,14,14)
__device__ float g_s2[4096 * 64 * 49];    // pooled conv2 output (N,64,7,7)
__device__ float g_fc1[4096 * 128];       // fc1 output (post relu)
__device__ float g_w2eff[64 * 153];       // conv2 effective weights: [o][17*9] stride 153

// ---------------------------------------------------------------------------
// prep: fold the 16 identical identity channels of conv1 into ONE conv2
// input channel: w_eff[o][144+k] = sum_{ci=16..31} w2[o][ci][k]
// ---------------------------------------------------------------------------
__global__ void pcf_prep(const float* __restrict__ w2g)
{
    int idx = blockIdx.x * 256 + threadIdx.x;
    if (idx >= 64 * 153) return;
    int o = idx / 153, k = idx - o * 153;
    float v;
    if (k < 144) {
        v = w2g[o * 288 + k];                 // gabor ci 0..15 verbatim
    } else {
        int kk = k - 144;                     // 0..8
        v = 0.f;
#pragma unroll
        for (int ci = 16; ci < 32; ci++) v += w2g[o * 288 + ci * 9 + kk];
    }
    g_w2eff[o * 153 + k] = v;
}

// ---------------------------------------------------------------------------
// k1: gabor-bank conv (16 ch) + ONE identity ch + relu + maxpool2 -> g_s1
// One block per image. Gabor weights recomputed per block (trivial).
// ---------------------------------------------------------------------------
__global__ void __launch_bounds__(256) pcf_k1(
    const float* __restrict__ x, const float* __restrict__ theta,
    const float* __restrict__ sigma, const float* __restrict__ gamma_,
    const float* __restrict__ lambd, const float* __restrict__ psi)
{
    __shared__ float ps[30][30];   // zero-padded 28x28 input
    __shared__ float gw[16][9];    // gabor filters
    const int n = blockIdx.x, t = threadIdx.x;

    for (int idx = t; idx < 900; idx += 256) ((float*)ps)[idx] = 0.f;
    __syncthreads();

    const float* xim = x + (size_t)n * 784;
    for (int idx = t; idx < 784; idx += 256) {
        int r = idx / 28, c = idx - r * 28;
        ps[r + 1][c + 1] = xim[idx];
    }
    if (t < 144) {
        int f = t / 9, k = t - f * 9;
        float xg = (float)(k / 3) - 1.f;
        float yg = (float)(k % 3) - 1.f;
        float th = theta[f];
        float cth = cosf(th), sth = sinf(th);
        float xt = xg * cth + yg * sth;
        float yt = -xg * sth + yg * cth;
        float sx = sigma[f];
        float sy = sigma[f] / gamma_[f];
        float env = expf(-0.5f * (xt * xt / (sx * sx) + yt * yt / (sy * sy)));
        float car = cosf(6.283185307179586f * xt / lambd[f] + psi[f]);
        gw[f][k] = env * car;
    }
    __syncthreads();

    float* out1 = g_s1 + (size_t)n * 3332;   // 17*196

    // identity channel (shared by all 16 original maps): maxpool(relu(x))
    if (t < 196) {
        int i = t / 14, j = t - (t / 14) * 14;
        float m = fmaxf(fmaxf(ps[2 * i + 1][2 * j + 1], ps[2 * i + 1][2 * j + 2]),
                        fmaxf(ps[2 * i + 2][2 * j + 1], ps[2 * i + 2][2 * j + 2]));
        out1[16 * 196 + t] = fmaxf(m, 0.f);
    }

    // gabor channels: conv 3x3 (pad 1) + relu + maxpool2
    for (int idx = t; idx < 16 * 196; idx += 256) {
        int c = idx / 196, p = idx - (idx / 196) * 196;
        int i = p / 14, j = p - (p / 14) * 14;
        float w[9];
#pragma unroll
        for (int k = 0; k < 9; k++) w[k] = gw[c][k];
        float m = -1e30f;
#pragma unroll
        for (int di = 0; di < 2; di++)
#pragma unroll
            for (int dj = 0; dj < 2; dj++) {
                float s = 0.f;
#pragma unroll
                for (int kh = 0; kh < 3; kh++)
#pragma unroll
                    for (int kw = 0; kw < 3; kw++)
                        s += ps[2 * i + di + kh][2 * j + dj + kw] * w[kh * 3 + kw];
                m = fmaxf(m, s);
            }
        out1[c * 196 + p] = fmaxf(m, 0.f);
    }
}

// ---------------------------------------------------------------------------
// k2: conv2 over 17 effective channels + bias + relu + maxpool2 -> g_s2
// One block per image, 448 threads = 14 warps.
// warp -> pooled row i = warp>>1 ; lane+warp parity -> output channel o (0..63)
// DUAL smem copies: si (even-pair u64 aligned) and sio (shifted by one float,
// so odd pairs are u64-aligned too). Inner loop: 8 LDS.128 + 42 FFMA2 per row,
// ZERO pack instructions.
// ---------------------------------------------------------------------------
__global__ void __launch_bounds__(448, 1) pcf_k2(const float* __restrict__ b2)
{
    extern __shared__ float sm[];
    float* si  = sm;            // 17 ch x 16 x 16 padded = 4352 floats
    float* sio = sm + 4352;     // shifted copy: sio[c] = si[c+1]
    float* ws  = sm + 8704;     // weights, per-o stride 153 (odd -> conflict-free)
    const int n = blockIdx.x;
    const int t = threadIdx.x;

    for (int idx = t; idx < 8704; idx += 448) sm[idx] = 0.f;
    for (int idx = t; idx < 64 * 153; idx += 448) ws[idx] = g_w2eff[idx];
    __syncthreads();

    const float* in = g_s1 + (size_t)n * 3332;
    for (int idx = t; idx < 3332; idx += 448) {
        int ci = idx / 196;
        int p = idx - ci * 196;
        int r = p / 14, c = p - r * 14;
        float v = in[idx];
        int base = ci * 256 + (r + 1) * 16 + (c + 1);
        si[base] = v;
        sio[base - 1] = v;     // sio[c] = si[c+1]
    }
    __syncthreads();

    const int warp = t >> 5, lane = t & 31;
    const int i = warp >> 1;                    // pooled row 0..6
    const int o = ((warp & 1) << 5) | lane;     // output channel 0..63

    u64t acc2[2][7];
#pragma unroll
    for (int lr = 0; lr < 2; lr++)
#pragma unroll
        for (int j = 0; j < 7; j++) acc2[lr][j] = 0ull;

    const float* wsbase = ws + o * 153;
    const int rowoff = 2 * i * 16;

#pragma unroll 1
    for (int ci = 0; ci < 17; ci++) {
        u64t wp[9];
#pragma unroll
        for (int k = 0; k < 9; k++) {
            float w = wsbase[ci * 9 + k];
            PACKF2(wp[k], w, w);
        }
        const u64t* rbe = (const u64t*)(si  + ci * 256 + rowoff);
        const u64t* rbo = (const u64t*)(sio + ci * 256 + rowoff);
#pragma unroll
        for (int r = 0; r < 4; r++) {
            u64t p0[8], p1[8];
            const ulonglong2* re = (const ulonglong2*)(rbe + r * 8);
            const ulonglong2* ro = (const ulonglong2*)(rbo + r * 8);
#pragma unroll
            for (int q = 0; q < 4; q++) {
                ulonglong2 ve = re[q];
                p0[2 * q] = ve.x; p0[2 * q + 1] = ve.y;
                ulonglong2 vo = ro[q];
                p1[2 * q] = vo.x; p1[2 * q + 1] = vo.y;
            }
#pragma unroll
            for (int lr = 0; lr < 2; lr++) {
                const int kh = r - lr;         // compile-time after unroll
                if (kh >= 0 && kh < 3) {
                    u64t w0 = wp[kh * 3], w1 = wp[kh * 3 + 1], w2v = wp[kh * 3 + 2];
#pragma unroll
                    for (int j = 0; j < 7; j++) {
                        FMA2(acc2[lr][j], p0[j], w0);
                        FMA2(acc2[lr][j], p1[j], w1);
                        FMA2(acc2[lr][j], p0[j + 1], w2v);
                    }
                }
            }
        }
    }

    const float b = b2[o];
    float* outp = g_s2 + (size_t)n * 3136 + o * 49 + i * 7;
#pragma unroll
    for (int j = 0; j < 7; j++) {
        union { u64t u; float2 f; } a0, a1;
        a0.u = acc2[0][j];
        a1.u = acc2[1][j];
        float m = fmaxf(fmaxf(a0.f.x, a0.f.y), fmaxf(a1.f.x, a1.f.y));
        outp[j] = fmaxf(m + b, 0.f);   // relu(max(conv)+b) == max(relu(conv+b))
    }
}

// ---------------------------------------------------------------------------
// k3: fc1 = relu(A(4096x3136) @ W^T(3136x128) + b) -> g_fc1
// (known-good R2 version: 64x64x32 tiles, 256 threads, micro 4x4 f32x2)
// ---------------------------------------------------------------------------
__global__ void __launch_bounds__(256) pcf_k3(
    const float* __restrict__ w1, const float* __restrict__ b1)
{
    __shared__ float As[32 * 64];
    __shared__ float Bs[32 * 64];
    const int t = threadIdx.x;
    const int tx = t & 15, ty = t >> 4;
    const int n0 = blockIdx.x * 64;
    const int m0 = blockIdx.y * 64;

    u64t acc2[4][2];
#pragma unroll
    for (int u = 0; u < 4; u++) { acc2[u][0] = 0ull; acc2[u][1] = 0ull; }

    for (int kt = 0; kt < 98; kt++) {
#pragma unroll
        for (int s = 0; s < 8; s++) {
            int idx = t + s * 256;
            int k = idx & 31, row = idx >> 5;
            int phys = (((row >> 2) ^ (k & 15)) << 2) | (row & 3);
            As[k * 64 + phys] = g_s2[(size_t)(n0 + row) * 3136 + kt * 32 + k];
            Bs[k * 64 + phys] = w1[(size_t)(m0 + row) * 3136 + kt * 32 + k];
        }
        __syncthreads();
#pragma unroll
        for (int kk = 0; kk < 32; kk++) {
            float4 a4 = *(const float4*)(As + kk * 64 + ((ty ^ (kk & 15)) << 2));
            float4 b4 = *(const float4*)(Bs + kk * 64 + ((tx ^ (kk & 15)) << 2));
            u64t bp0, bp1;
            PACKF2(bp0, b4.x, b4.y);
            PACKF2(bp1, b4.z, b4.w);
            float av[4] = { a4.x, a4.y, a4.z, a4.w };
#pragma unroll
            for (int u = 0; u < 4; u++) {
                u64t ap;
                PACKF2(ap, av[u], av[u]);
                FMA2(acc2[u][0], bp0, ap);
                FMA2(acc2[u][1], bp1, ap);
            }
        }
        __syncthreads();
    }

#pragma unroll
    for (int u = 0; u < 4; u++) {
        int nrow = n0 + ty * 4 + u;
#pragma unroll
        for (int p = 0; p < 2; p++) {
            union { u64t v; float2 f; } cv;
            cv.v = acc2[u][p];
            int m = m0 + tx * 4 + p * 2;
            g_fc1[(size_t)nrow * 128 + m]     = fmaxf(cv.f.x + b1[m], 0.f);
            g_fc1[(size_t)nrow * 128 + m + 1] = fmaxf(cv.f.y + b1[m + 1], 0.f);
        }
    }
}

// ---------------------------------------------------------------------------
// k4: fc2 = g_fc1 @ W2^T + b2 -> out (4096x10). K=128, trivial.
// ---------------------------------------------------------------------------
__global__ void __launch_bounds__(256) pcf_k4(
    const float* __restrict__ w2, const float* __restrict__ b2,
    float* __restrict__ out)
{
    int gid = blockIdx.x * 256 + threadIdx.x;
    if (gid >= 4096 * 10) return;
    int nrow = gid / 10, o = gid - nrow * 10;
    const float4* a = (const float4*)(g_fc1 + (size_t)nrow * 128);
    const float4* w = (const float4*)(w2 + o * 128);
    float s = b2[o];
#pragma unroll
    for (int q = 0; q < 32; q++) {
        float4 av = a[q], wv = w[q];
        s += av.x * wv.x + av.y * wv.y + av.z * wv.z + av.w * wv.w;
    }
    out[gid] = s;
}

// ---------------------------------------------------------------------------
extern "C" void kernel_launch(void* const* d_in, const int* in_sizes, int n_in,
                              void* d_out, int out_size)
{
    const float* x       = (const float*)d_in[0];
    const float* theta   = (const float*)d_in[1];
    const float* sigma   = (const float*)d_in[2];
    const float* gamma_  = (const float*)d_in[3];
    const float* lambd   = (const float*)d_in[4];
    const float* psi     = (const float*)d_in[5];
    const float* conv2_w = (const float*)d_in[6];
    const float* conv2_b = (const float*)d_in[7];
    const float* fc1_w   = (const float*)d_in[8];
    const float* fc1_b   = (const float*)d_in[9];
    const float* fc2_w   = (const float*)d_in[10];
    const float* fc2_b   = (const float*)d_in[11];
    float* out = (float*)d_out;

    const int k2_smem = (8704 + 64 * 153) * 4;   // 73984 bytes -> 3 blocks/SM
    cudaFuncSetAttribute(pcf_k2, cudaFuncAttributeMaxDynamicSharedMemorySize, k2_smem);

    pcf_prep<<<39, 256>>>(conv2_w);
    pcf_k1<<<4096, 256>>>(x, theta, sigma, gamma_, lambd, psi);
    pcf_k2<<<4096, 448, k2_smem>>>(conv2_b);
    pcf_k3<<<dim3(64, 2), 256>>>(fc1_w, fc1_b);
    pcf_k4<<<160, 256>>>(fc2_w, fc2_b, out);
}

// round 11
// speedup vs baseline: 1.9654x; 1.1321x over previous
#include <cuda_runtime.h>
#include <math.h>

typedef unsigned long long u64t;

// Packed f32x2 FMA (Blackwell packed fp32 path)
#define FMA2(d, a, b) asm("fma.rn.f32x2 %0, %1, %2, %0;" : "+l"(d) : "l"(a), "l"(b))
#define PACKF2(o, lo, hi) asm("mov.b64 %0, {%1, %2};" : "=l"(o) : "r"(__float_as_uint(lo)), "r"(__float_as_uint(hi)))

// Scratch (allocation-free rule: __device__ globals)
__device__ float g_s1[4096 * 17 * 196];   // pooled conv1 output (N,17,14,14)
__device__ float g_s2[4096 * 64 * 49];    // pooled conv2 output (N,64,7,7)
__device__ float g_fc1[4096 * 128];       // fc1 output (post relu)
__device__ float g_fc1p[7][4096 * 128];   // fc1 split-K partials
__device__ float g_w2eff[64 * 153];       // conv2 effective weights: [o][17*9] stride 153

// ---------------------------------------------------------------------------
// prep: fold the 16 identical identity channels of conv1 into ONE conv2
// input channel: w_eff[o][144+k] = sum_{ci=16..31} w2[o][ci][k]
// ---------------------------------------------------------------------------
__global__ void pcf_prep(const float* __restrict__ w2g)
{
    int idx = blockIdx.x * 256 + threadIdx.x;
    if (idx >= 64 * 153) return;
    int o = idx / 153, k = idx - o * 153;
    float v;
    if (k < 144) {
        v = w2g[o * 288 + k];                 // gabor ci 0..15 verbatim
    } else {
        int kk = k - 144;                     // 0..8
        v = 0.f;
#pragma unroll
        for (int ci = 16; ci < 32; ci++) v += w2g[o * 288 + ci * 9 + kk];
    }
    g_w2eff[o * 153 + k] = v;
}

// ---------------------------------------------------------------------------
// k1: gabor-bank conv (16 ch) + ONE identity ch + relu + maxpool2 -> g_s1
// ---------------------------------------------------------------------------
__global__ void __launch_bounds__(256) pcf_k1(
    const float* __restrict__ x, const float* __restrict__ theta,
    const float* __restrict__ sigma, const float* __restrict__ gamma_,
    const float* __restrict__ lambd, const float* __restrict__ psi)
{
    __shared__ float ps[30][30];   // zero-padded 28x28 input
    __shared__ float gw[16][9];    // gabor filters
    const int n = blockIdx.x, t = threadIdx.x;

    for (int idx = t; idx < 900; idx += 256) ((float*)ps)[idx] = 0.f;
    __syncthreads();

    const float* xim = x + (size_t)n * 784;
    for (int idx = t; idx < 784; idx += 256) {
        int r = idx / 28, c = idx - r * 28;
        ps[r + 1][c + 1] = xim[idx];
    }
    if (t < 144) {
        int f = t / 9, k = t - f * 9;
        float xg = (float)(k / 3) - 1.f;
        float yg = (float)(k % 3) - 1.f;
        float th = theta[f];
        float cth = cosf(th), sth = sinf(th);
        float xt = xg * cth + yg * sth;
        float yt = -xg * sth + yg * cth;
        float sx = sigma[f];
        float sy = sigma[f] / gamma_[f];
        float env = expf(-0.5f * (xt * xt / (sx * sx) + yt * yt / (sy * sy)));
        float car = cosf(6.283185307179586f * xt / lambd[f] + psi[f]);
        gw[f][k] = env * car;
    }
    __syncthreads();

    float* out1 = g_s1 + (size_t)n * 3332;   // 17*196

    // identity channel: maxpool(relu(x))
    if (t < 196) {
        int i = t / 14, j = t - (t / 14) * 14;
        float m = fmaxf(fmaxf(ps[2 * i + 1][2 * j + 1], ps[2 * i + 1][2 * j + 2]),
                        fmaxf(ps[2 * i + 2][2 * j + 1], ps[2 * i + 2][2 * j + 2]));
        out1[16 * 196 + t] = fmaxf(m, 0.f);
    }

    // gabor channels: conv 3x3 (pad 1) + relu + maxpool2
    for (int idx = t; idx < 16 * 196; idx += 256) {
        int c = idx / 196, p = idx - (idx / 196) * 196;
        int i = p / 14, j = p - (p / 14) * 14;
        float w[9];
#pragma unroll
        for (int k = 0; k < 9; k++) w[k] = gw[c][k];
        float m = -1e30f;
#pragma unroll
        for (int di = 0; di < 2; di++)
#pragma unroll
            for (int dj = 0; dj < 2; dj++) {
                float s = 0.f;
#pragma unroll
                for (int kh = 0; kh < 3; kh++)
#pragma unroll
                    for (int kw = 0; kw < 3; kw++)
                        s += ps[2 * i + di + kh][2 * j + dj + kw] * w[kh * 3 + kw];
                m = fmaxf(m, s);
            }
        out1[c * 196 + p] = fmaxf(m, 0.f);
    }
}

// ---------------------------------------------------------------------------
// k2: conv2 over 17 effective channels + bias + relu + maxpool2 -> g_s2
// One block per image, 224 threads = 7 warps.
// warp -> pooled row i (0..6); lane -> channel PAIR (o, o+32): each input
// row load is reused for 2 output channels -> LDS per FMA halved.
// Dual smem copies (si / sio shifted by one float): all pairs are direct
// u64-aligned LDS.128, zero packs. launch_bounds(224,2) -> 2 blocks/SM.
// ---------------------------------------------------------------------------
__global__ void __launch_bounds__(224, 2) pcf_k2(const float* __restrict__ b2)
{
    extern __shared__ float sm[];
    float* si  = sm;            // 17 ch x 16 x 16 padded = 4352 floats
    float* sio = sm + 4352;     // shifted copy: sio[c] = si[c+1]
    float* ws  = sm + 8704;     // weights, per-o stride 153 (odd -> conflict-free)
    const int n = blockIdx.x;
    const int t = threadIdx.x;

    for (int idx = t; idx < 8704; idx += 224) sm[idx] = 0.f;
    for (int idx = t; idx < 64 * 153; idx += 224) ws[idx] = g_w2eff[idx];
    __syncthreads();

    const float* in = g_s1 + (size_t)n * 3332;
    for (int idx = t; idx < 3332; idx += 224) {
        int ci = idx / 196;
        int p = idx - ci * 196;
        int r = p / 14, c = p - r * 14;
        float v = in[idx];
        int base = ci * 256 + (r + 1) * 16 + (c + 1);
        si[base] = v;
        sio[base - 1] = v;     // sio[c] = si[c+1]
    }
    __syncthreads();

    const int warp = t >> 5, lane = t & 31;
    const int i = warp;                   // pooled row 0..6
    const int o0 = lane, o1 = lane + 32;  // channel pair

    u64t acc[2][2][7];
#pragma unroll
    for (int oc = 0; oc < 2; oc++)
#pragma unroll
        for (int lr = 0; lr < 2; lr++)
#pragma unroll
            for (int j = 0; j < 7; j++) acc[oc][lr][j] = 0ull;

    const float* wb0 = ws + o0 * 153;
    const float* wb1 = ws + o1 * 153;
    const int rowoff = 2 * i * 16;

#pragma unroll 1
    for (int ci = 0; ci < 17; ci++) {
        u64t wp0[9], wp1[9];
#pragma unroll
        for (int k = 0; k < 9; k++) {
            float w = wb0[ci * 9 + k];
            PACKF2(wp0[k], w, w);
            float v = wb1[ci * 9 + k];
            PACKF2(wp1[k], v, v);
        }
        const u64t* rbe = (const u64t*)(si  + ci * 256 + rowoff);
        const u64t* rbo = (const u64t*)(sio + ci * 256 + rowoff);
#pragma unroll
        for (int r = 0; r < 4; r++) {
            u64t p0[8], p1[8];
            const ulonglong2* re = (const ulonglong2*)(rbe + r * 8);
            const ulonglong2* ro = (const ulonglong2*)(rbo + r * 8);
#pragma unroll
            for (int q = 0; q < 4; q++) {
                ulonglong2 ve = re[q];
                p0[2 * q] = ve.x; p0[2 * q + 1] = ve.y;
                ulonglong2 vo = ro[q];
                p1[2 * q] = vo.x; p1[2 * q + 1] = vo.y;
            }
#pragma unroll
            for (int lr = 0; lr < 2; lr++) {
                const int kh = r - lr;         // compile-time after unroll
                if (kh >= 0 && kh < 3) {
                    u64t a0 = wp0[kh * 3], a1 = wp0[kh * 3 + 1], a2 = wp0[kh * 3 + 2];
                    u64t c0 = wp1[kh * 3], c1 = wp1[kh * 3 + 1], c2 = wp1[kh * 3 + 2];
#pragma unroll
                    for (int j = 0; j < 7; j++) {
                        FMA2(acc[0][lr][j], p0[j], a0);
                        FMA2(acc[0][lr][j], p1[j], a1);
                        FMA2(acc[0][lr][j], p0[j + 1], a2);
                        FMA2(acc[1][lr][j], p0[j], c0);
                        FMA2(acc[1][lr][j], p1[j], c1);
                        FMA2(acc[1][lr][j], p0[j + 1], c2);
                    }
                }
            }
        }
    }

#pragma unroll
    for (int oc = 0; oc < 2; oc++) {
        const int o = oc ? o1 : o0;
        const float b = b2[o];
        float* outp = g_s2 + (size_t)n * 3136 + o * 49 + i * 7;
#pragma unroll
        for (int j = 0; j < 7; j++) {
            union { u64t u; float2 f; } a0, a1;
            a0.u = acc[oc][0][j];
            a1.u = acc[oc][1][j];
            float m = fmaxf(fmaxf(a0.f.x, a0.f.y), fmaxf(a1.f.x, a1.f.y));
            outp[j] = fmaxf(m + b, 0.f);
        }
    }
}

// ---------------------------------------------------------------------------
// k3: fc1 partials, split-K x7. Grid (64 n-tiles, 2 m-tiles, 7 k-splits).
// Each block: 64x64 tile over kt in [ks*14, ks*14+14), writes raw partial
// to g_fc1p[ks]. Same proven inner loop as before; occupancy 6 blocks/SM.
// ---------------------------------------------------------------------------
__global__ void __launch_bounds__(256) pcf_k3(const float* __restrict__ w1)
{
    __shared__ float As[32 * 64];
    __shared__ float Bs[32 * 64];
    const int t = threadIdx.x;
    const int tx = t & 15, ty = t >> 4;
    const int n0 = blockIdx.x * 64;
    const int m0 = blockIdx.y * 64;
    const int ks = blockIdx.z;

    u64t acc2[4][2];
#pragma unroll
    for (int u = 0; u < 4; u++) { acc2[u][0] = 0ull; acc2[u][1] = 0ull; }

    for (int kt = ks * 14; kt < ks * 14 + 14; kt++) {
#pragma unroll
        for (int s = 0; s < 8; s++) {
            int idx = t + s * 256;
            int k = idx & 31, row = idx >> 5;
            int phys = (((row >> 2) ^ (k & 15)) << 2) | (row & 3);
            As[k * 64 + phys] = g_s2[(size_t)(n0 + row) * 3136 + kt * 32 + k];
            Bs[k * 64 + phys] = w1[(size_t)(m0 + row) * 3136 + kt * 32 + k];
        }
        __syncthreads();
#pragma unroll
        for (int kk = 0; kk < 32; kk++) {
            float4 a4 = *(const float4*)(As + kk * 64 + ((ty ^ (kk & 15)) << 2));
            float4 b4 = *(const float4*)(Bs + kk * 64 + ((tx ^ (kk & 15)) << 2));
            u64t bp0, bp1;
            PACKF2(bp0, b4.x, b4.y);
            PACKF2(bp1, b4.z, b4.w);
            float av[4] = { a4.x, a4.y, a4.z, a4.w };
#pragma unroll
            for (int u = 0; u < 4; u++) {
                u64t ap;
                PACKF2(ap, av[u], av[u]);
                FMA2(acc2[u][0], bp0, ap);
                FMA2(acc2[u][1], bp1, ap);
            }
        }
        __syncthreads();
    }

    float* pout = g_fc1p[ks];
#pragma unroll
    for (int u = 0; u < 4; u++) {
        int nrow = n0 + ty * 4 + u;
#pragma unroll
        for (int p = 0; p < 2; p++) {
            union { u64t v; float2 f; } cv;
            cv.v = acc2[u][p];
            int m = m0 + tx * 4 + p * 2;
            pout[(size_t)nrow * 128 + m]     = cv.f.x;
            pout[(size_t)nrow * 128 + m + 1] = cv.f.y;
        }
    }
}

// ---------------------------------------------------------------------------
// k3r: reduce 7 partials + bias + relu -> g_fc1. float4 vectorized.
// ---------------------------------------------------------------------------
__global__ void __launch_bounds__(256) pcf_k3r(const float* __restrict__ b1)
{
    int gid = blockIdx.x * 256 + threadIdx.x;   // 512*256 = 131072 = 4096*32
    int col4 = gid & 31;
    float4 s = ((const float4*)g_fc1p[0])[gid];
#pragma unroll
    for (int p = 1; p < 7; p++) {
        float4 v = ((const float4*)g_fc1p[p])[gid];
        s.x += v.x; s.y += v.y; s.z += v.z; s.w += v.w;
    }
    float4 b = ((const float4*)b1)[col4];
    s.x = fmaxf(s.x + b.x, 0.f);
    s.y = fmaxf(s.y + b.y, 0.f);
    s.z = fmaxf(s.z + b.z, 0.f);
    s.w = fmaxf(s.w + b.w, 0.f);
    ((float4*)g_fc1)[gid] = s;
}

// ---------------------------------------------------------------------------
// k4: fc2 = g_fc1 @ W2^T + b2 -> out (4096x10). K=128, trivial.
// ---------------------------------------------------------------------------
__global__ void __launch_bounds__(256) pcf_k4(
    const float* __restrict__ w2, const float* __restrict__ b2,
    float* __restrict__ out)
{
    int gid = blockIdx.x * 256 + threadIdx.x;
    if (gid >= 4096 * 10) return;
    int nrow = gid / 10, o = gid - nrow * 10;
    const float4* a = (const float4*)(g_fc1 + (size_t)nrow * 128);
    const float4* w = (const float4*)(w2 + o * 128);
    float s = b2[o];
#pragma unroll
    for (int q = 0; q < 32; q++) {
        float4 av = a[q], wv = w[q];
        s += av.x * wv.x + av.y * wv.y + av.z * wv.z + av.w * wv.w;
    }
    out[gid] = s;
}

// ---------------------------------------------------------------------------
extern "C" void kernel_launch(void* const* d_in, const int* in_sizes, int n_in,
                              void* d_out, int out_size)
{
    const float* x       = (const float*)d_in[0];
    const float* theta   = (const float*)d_in[1];
    const float* sigma   = (const float*)d_in[2];
    const float* gamma_  = (const float*)d_in[3];
    const float* lambd   = (const float*)d_in[4];
    const float* psi     = (const float*)d_in[5];
    const float* conv2_w = (const float*)d_in[6];
    const float* conv2_b = (const float*)d_in[7];
    const float* fc1_w   = (const float*)d_in[8];
    const float* fc1_b   = (const float*)d_in[9];
    const float* fc2_w   = (const float*)d_in[10];
    const float* fc2_b   = (const float*)d_in[11];
    float* out = (float*)d_out;

    const int k2_smem = (8704 + 64 * 153) * 4;   // 73984 bytes -> 2 blocks/SM
    cudaFuncSetAttribute(pcf_k2, cudaFuncAttributeMaxDynamicSharedMemorySize, k2_smem);

    pcf_prep<<<39, 256>>>(conv2_w);
    pcf_k1<<<4096, 256>>>(x, theta, sigma, gamma_, lambd, psi);
    pcf_k2<<<4096, 224, k2_smem>>>(conv2_b);
    pcf_k3<<<dim3(64, 2, 7), 256>>>(fc1_w);
    pcf_k3r<<<512, 256>>>(fc1_b);
    pcf_k4<<<160, 256>>>(fc2_w, fc2_b, out);
}

// round 13
// speedup vs baseline: 2.1869x; 1.1127x over previous
#include <cuda_runtime.h>
#include <cuda_fp16.h>
#include <math.h>
#include <stdint.h>

typedef unsigned long long u64t;

// ---------------- packed fp32 (k3) ----------------
#define FMA2(d, a, b) asm("fma.rn.f32x2 %0, %1, %2, %0;" : "+l"(d) : "l"(a), "l"(b))
#define PACKF2(o, lo, hi) asm("mov.b64 %0, {%1, %2};" : "=l"(o) : "r"(__float_as_uint(lo)), "r"(__float_as_uint(hi)))

// ---------------- warp MMA helpers (portable PTX, no tcgen05) ----------------
#define LDMATRIX_X4(r0, r1, r2, r3, addr) \
    asm volatile("ldmatrix.sync.aligned.m8n8.x4.shared.b16 {%0,%1,%2,%3}, [%4];" \
                 : "=r"(r0), "=r"(r1), "=r"(r2), "=r"(r3) : "r"(addr))
#define MMA16816(c0, c1, c2, c3, a0, a1, a2, a3, b0, b1) \
    asm volatile("mma.sync.aligned.m16n8k16.row.col.f32.f16.f16.f32 " \
                 "{%0,%1,%2,%3}, {%4,%5,%6,%7}, {%8,%9}, {%0,%1,%2,%3};" \
                 : "+f"(c0), "+f"(c1), "+f"(c2), "+f"(c3) \
                 : "r"(a0), "r"(a1), "r"(a2), "r"(a3), "r"(b0), "r"(b1))

__device__ __forceinline__ uint32_t smem_u32(const void* p) {
    uint32_t a;
    asm("{ .reg .u64 t; cvta.to.shared.u64 t, %1; cvt.u32.u64 %0, t; }" : "=r"(a) : "l"(p));
    return a;
}

// ---------------- scratch ----------------
__device__ __align__(16) __half g_s1h[4096 * 256 * 32];   // conv1 out, fp16 HWC: [n][pos 16x16][ci 32pad]
__device__ float g_s2[4096 * 64 * 49];                    // pooled conv2 output
__device__ float g_fc1[4096 * 128];
__device__ float g_fc1p[7][4096 * 128];
__device__ uint32_t g_wpk[9 * 2 * 8 * 32 * 2];            // B fragments: [tap][kt][ntile][lane][2]

// ---------------------------------------------------------------------------
// prep: build mma B-fragments of effective conv2 weights (17-ch fold, fp16).
// B[k][n] fragment (m16n8k16, .col): lane l holds {B[k0][n],B[k0+1][n]} and
// {B[k0+8][n],B[k0+9][n]}, k0=(l%4)*2, n=ntile*8+l/4. k axis = ci (K=32 pad).
// ---------------------------------------------------------------------------
__global__ void pcf_prep(const float* __restrict__ w2g)
{
    int idx = blockIdx.x * 256 + threadIdx.x;
    if (idx >= 4608) return;                 // 9*2*8*32
    int lane = idx & 31;
    int ntg  = (idx >> 5) & 7;
    int kt   = (idx >> 8) & 1;
    int tap  = idx >> 9;                     // 0..8
    int n    = ntg * 8 + (lane >> 2);
    int k0   = (lane & 3) * 2;

    float v[4];
#pragma unroll
    for (int j = 0; j < 4; j++) {
        int ci = kt * 16 + k0 + (j & 1) + ((j >> 1) * 8);
        float w = 0.f;
        if (ci < 16) {
            w = w2g[n * 288 + ci * 9 + tap];
        } else if (ci == 16) {
#pragma unroll
            for (int c = 16; c < 32; c++) w = w + w2g[n * 288 + c * 9 + tap];
        }
        v[j] = w;
    }
    __half h0 = __float2half(v[0]), h1 = __float2half(v[1]);
    __half h2 = __float2half(v[2]), h3 = __float2half(v[3]);
    uint32_t u0 = (uint32_t)__half_as_ushort(h0) | ((uint32_t)__half_as_ushort(h1) << 16);
    uint32_t u1 = (uint32_t)__half_as_ushort(h2) | ((uint32_t)__half_as_ushort(h3) << 16);
    g_wpk[idx * 2]     = u0;
    g_wpk[idx * 2 + 1] = u1;
}

// ---------------------------------------------------------------------------
// k1: gabor conv (16 ch) + identity ch + relu + maxpool2 -> g_s1h fp16 HWC.
// Grid rows/cols 0..15; real pooled pixels at 1..14 (border = conv2 pad);
// ci 17..31 zero pad.
// ---------------------------------------------------------------------------
__global__ void __launch_bounds__(256) pcf_k1(
    const float* __restrict__ x, const float* __restrict__ theta,
    const float* __restrict__ sigma, const float* __restrict__ gamma_,
    const float* __restrict__ lambd, const float* __restrict__ psi)
{
    __shared__ float ps[30][30];
    __shared__ float gw[16][9];
    const int n = blockIdx.x, t = threadIdx.x;

    for (int idx = t; idx < 900; idx += 256) ((float*)ps)[idx] = 0.f;
    {   // zero the whole fp16 HWC tile (pad channels + borders)
        uint4* z = (uint4*)(g_s1h + (size_t)n * 8192);
        for (int idx = t; idx < 1024; idx += 256) z[idx] = make_uint4(0, 0, 0, 0);
    }
    __syncthreads();

    const float* xim = x + (size_t)n * 784;
    for (int idx = t; idx < 784; idx += 256) {
        int r = idx / 28, c = idx - r * 28;
        ps[r + 1][c + 1] = xim[idx];
    }
    if (t < 144) {
        int f = t / 9, k = t - f * 9;
        float xg = (float)(k / 3) - 1.f;
        float yg = (float)(k % 3) - 1.f;
        float th = theta[f];
        float cth = cosf(th), sth = sinf(th);
        float xt = xg * cth + yg * sth;
        float yt = -xg * sth + yg * cth;
        float sx = sigma[f];
        float sy = sigma[f] / gamma_[f];
        float env = expf(-0.5f * (xt * xt / (sx * sx) + yt * yt / (sy * sy)));
        float car = cosf(6.283185307179586f * xt / lambd[f] + psi[f]);
        gw[f][k] = env * car;
    }
    __syncthreads();

    __half* out1 = g_s1h + (size_t)n * 8192;

    // identity channel ci=16
    if (t < 196) {
        int i = t / 14, j = t - (t / 14) * 14;
        float m = fmaxf(fmaxf(ps[2 * i + 1][2 * j + 1], ps[2 * i + 1][2 * j + 2]),
                        fmaxf(ps[2 * i + 2][2 * j + 1], ps[2 * i + 2][2 * j + 2]));
        out1[((i + 1) * 16 + (j + 1)) * 32 + 16] = __float2half(fmaxf(m, 0.f));
    }

    // gabor channels ci 0..15
    for (int idx = t; idx < 16 * 196; idx += 256) {
        int c = idx / 196, p = idx - (idx / 196) * 196;
        int i = p / 14, j = p - (p / 14) * 14;
        float w[9];
#pragma unroll
        for (int k = 0; k < 9; k++) w[k] = gw[c][k];
        float m = -1e30f;
#pragma unroll
        for (int di = 0; di < 2; di++)
#pragma unroll
            for (int dj = 0; dj < 2; dj++) {
                float s = 0.f;
#pragma unroll
                for (int kh = 0; kh < 3; kh++)
#pragma unroll
                    for (int kw = 0; kw < 3; kw++)
                        s += ps[2 * i + di + kh][2 * j + dj + kw] * w[kh * 3 + kw];
                m = fmaxf(m, s);
            }
        out1[((i + 1) * 16 + (j + 1)) * 32 + c] = __float2half(fmaxf(m, 0.f));
    }
}

// ---------------------------------------------------------------------------
// k2m: conv2 via warp HMMA (mma.sync m16n8k16 fp16, fp32 acc), direct-tap.
// One CTA per image, 128 threads = 4 warps; warp w owns channels 16w..16w+15.
// M = positions quad-major (quad*4+corner), 13 m-tiles of 16 cover 49 pooled
// quads. A fragments ldmatrix'd straight from the fp16 HWC smem buffer with
// per-tap address shifts (zero im2col). B fragments: 72 regs, loaded once.
// Epilogue: shfl-quad maxpool -> smem -> coalesced bias+relu store.
// ---------------------------------------------------------------------------
__global__ void __launch_bounds__(128) pcf_k2m(const float* __restrict__ b2)
{
    extern __shared__ char smraw[];
    float* sO = (float*)(smraw + 16384);     // [64][52]
    const int n = blockIdx.x, t = threadIdx.x;
    const int warp = t >> 5, lane = t & 31;

    // stage fp16 HWC input (16 KB)
    {
        const uint4* src = (const uint4*)(g_s1h + (size_t)n * 8192);
        uint4* dst = (uint4*)smraw;
        for (int i = t; i < 1024; i += 128) dst[i] = src[i];
    }

    // load B fragments (once)
    uint32_t B[9][2][2][2];
#pragma unroll
    for (int tap = 0; tap < 9; tap++)
#pragma unroll
        for (int kt = 0; kt < 2; kt++)
#pragma unroll
            for (int nt = 0; nt < 2; nt++) {
                int idx = ((tap * 2 + kt) * 8 + (warp * 2 + nt)) * 32 + lane;
                uint2 v = ((const uint2*)g_wpk)[idx];
                B[tap][kt][nt][0] = v.x;
                B[tap][kt][nt][1] = v.y;
            }
    __syncthreads();

    const uint32_t sb = smem_u32(smraw);
    const int m = lane & 15;                 // A row this lane addresses

    for (int tile = 0; tile < 13; tile++) {
        // lane's A row -> position (quad-major, clamped for pad quads 49-51)
        int qg = tile * 4 + (m >> 2);
        int qv = (qg <= 48) ? qg : 48;
        int qi = qv / 7, qj = qv - qi * 7;
        int pi = 2 * qi + ((m >> 1) & 1);
        int pj = 2 * qj + (m & 1);
        uint32_t a_base = sb + (uint32_t)((pi * 16 + pj) * 64) + (uint32_t)(lane & 16);

        float acc[2][4];
#pragma unroll
        for (int nt = 0; nt < 2; nt++)
#pragma unroll
            for (int k = 0; k < 4; k++) acc[nt][k] = 0.f;

#pragma unroll
        for (int kh = 0; kh < 3; kh++)
#pragma unroll
            for (int kw = 0; kw < 3; kw++) {
                const int tap = kh * 3 + kw;
                const uint32_t tshift = (uint32_t)((kh * 16 + kw) * 64);
#pragma unroll
                for (int kt = 0; kt < 2; kt++) {
                    uint32_t a0, a1, a2, a3;
                    LDMATRIX_X4(a0, a1, a2, a3, a_base + tshift + kt * 32);
                    MMA16816(acc[0][0], acc[0][1], acc[0][2], acc[0][3],
                             a0, a1, a2, a3, B[tap][kt][0][0], B[tap][kt][0][1]);
                    MMA16816(acc[1][0], acc[1][1], acc[1][2], acc[1][3],
                             a0, a1, a2, a3, B[tap][kt][1][0], B[tap][kt][1][1]);
                }
            }

        // maxpool over the 4 corners (rows within a quad are lane-adjacent:
        // corner bits = bits 2-3 of lane via D row = lane/4)
        const bool wr = ((lane >> 2) & 3) == 0;
#pragma unroll
        for (int nt = 0; nt < 2; nt++)
#pragma unroll
            for (int k = 0; k < 4; k++) {
                float v = acc[nt][k];
                v = fmaxf(v, __shfl_xor_sync(0xffffffffu, v, 4));
                v = fmaxf(v, __shfl_xor_sync(0xffffffffu, v, 8));
                if (wr) {
                    int ql = (lane >> 4) + ((k >> 1) << 1);   // d0/d1 quads 0,1; d2/d3 quads 2,3
                    int q = tile * 4 + ql;                    // <= 51
                    int ch = warp * 16 + nt * 8 + (lane & 3) * 2 + (k & 1);
                    sO[ch * 52 + q] = v;
                }
            }
    }
    __syncthreads();

    // bias + relu + coalesced store
    float* outp = g_s2 + (size_t)n * 3136;
    for (int idx = t; idx < 3136; idx += 128) {
        int ch = idx / 49, p = idx - ch * 49;
        outp[idx] = fmaxf(sO[ch * 52 + p] + __ldg(b2 + ch), 0.f);
    }
}

// ---------------------------------------------------------------------------
// k3: fc1 partials, split-K x7 (unchanged, proven)
// ---------------------------------------------------------------------------
__global__ void __launch_bounds__(256) pcf_k3(const float* __restrict__ w1)
{
    __shared__ float As[32 * 64];
    __shared__ float Bs[32 * 64];
    const int t = threadIdx.x;
    const int tx = t & 15, ty = t >> 4;
    const int n0 = blockIdx.x * 64;
    const int m0 = blockIdx.y * 64;
    const int ks = blockIdx.z;

    u64t acc2[4][2];
#pragma unroll
    for (int u = 0; u < 4; u++) { acc2[u][0] = 0ull; acc2[u][1] = 0ull; }

    for (int kt = ks * 14; kt < ks * 14 + 14; kt++) {
#pragma unroll
        for (int s = 0; s < 8; s++) {
            int idx = t + s * 256;
            int k = idx & 31, row = idx >> 5;
            int phys = (((row >> 2) ^ (k & 15)) << 2) | (row & 3);
            As[k * 64 + phys] = g_s2[(size_t)(n0 + row) * 3136 + kt * 32 + k];
            Bs[k * 64 + phys] = w1[(size_t)(m0 + row) * 3136 + kt * 32 + k];
        }
        __syncthreads();
#pragma unroll
        for (int kk = 0; kk < 32; kk++) {
            float4 a4 = *(const float4*)(As + kk * 64 + ((ty ^ (kk & 15)) << 2));
            float4 b4 = *(const float4*)(Bs + kk * 64 + ((tx ^ (kk & 15)) << 2));
            u64t bp0, bp1;
            PACKF2(bp0, b4.x, b4.y);
            PACKF2(bp1, b4.z, b4.w);
            float av[4] = { a4.x, a4.y, a4.z, a4.w };
#pragma unroll
            for (int u = 0; u < 4; u++) {
                u64t ap;
                PACKF2(ap, av[u], av[u]);
                FMA2(acc2[u][0], bp0, ap);
                FMA2(acc2[u][1], bp1, ap);
            }
        }
        __syncthreads();
    }

    float* pout = g_fc1p[ks];
#pragma unroll
    for (int u = 0; u < 4; u++) {
        int nrow = n0 + ty * 4 + u;
#pragma unroll
        for (int p = 0; p < 2; p++) {
            union { u64t v; float2 f; } cv;
            cv.v = acc2[u][p];
            int mm = m0 + tx * 4 + p * 2;
            pout[(size_t)nrow * 128 + mm]     = cv.f.x;
            pout[(size_t)nrow * 128 + mm + 1] = cv.f.y;
        }
    }
}

__global__ void __launch_bounds__(256) pcf_k3r(const float* __restrict__ b1)
{
    int gid = blockIdx.x * 256 + threadIdx.x;
    int col4 = gid & 31;
    float4 s = ((const float4*)g_fc1p[0])[gid];
#pragma unroll
    for (int p = 1; p < 7; p++) {
        float4 v = ((const float4*)g_fc1p[p])[gid];
        s.x += v.x; s.y += v.y; s.z += v.z; s.w += v.w;
    }
    float4 b = ((const float4*)b1)[col4];
    s.x = fmaxf(s.x + b.x, 0.f);
    s.y = fmaxf(s.y + b.y, 0.f);
    s.z = fmaxf(s.z + b.z, 0.f);
    s.w = fmaxf(s.w + b.w, 0.f);
    ((float4*)g_fc1)[gid] = s;
}

__global__ void __launch_bounds__(256) pcf_k4(
    const float* __restrict__ w2, const float* __restrict__ b2,
    float* __restrict__ out)
{
    int gid = blockIdx.x * 256 + threadIdx.x;
    if (gid >= 4096 * 10) return;
    int nrow = gid / 10, o = gid - nrow * 10;
    const float4* a = (const float4*)(g_fc1 + (size_t)nrow * 128);
    const float4* w = (const float4*)(w2 + o * 128);
    float s = b2[o];
#pragma unroll
    for (int q = 0; q < 32; q++) {
        float4 av = a[q], wv = w[q];
        s += av.x * wv.x + av.y * wv.y + av.z * wv.z + av.w * wv.w;
    }
    out[gid] = s;
}

// ---------------------------------------------------------------------------
extern "C" void kernel_launch(void* const* d_in, const int* in_sizes, int n_in,
                              void* d_out, int out_size)
{
    const float* x       = (const float*)d_in[0];
    const float* theta   = (const float*)d_in[1];
    const float* sigma   = (const float*)d_in[2];
    const float* gamma_  = (const float*)d_in[3];
    const float* lambd   = (const float*)d_in[4];
    const float* psi     = (const float*)d_in[5];
    const float* conv2_w = (const float*)d_in[6];
    const float* conv2_b = (const float*)d_in[7];
    const float* fc1_w   = (const float*)d_in[8];
    const float* fc1_b   = (const float*)d_in[9];
    const float* fc2_w   = (const float*)d_in[10];
    const float* fc2_b   = (const float*)d_in[11];
    float* out = (float*)d_out;

    const int k2m_smem = 16384 + 64 * 52 * 4;   // 29696 bytes

    pcf_prep<<<18, 256>>>(conv2_w);
    pcf_k1<<<4096, 256>>>(x, theta, sigma, gamma_, lambd, psi);
    pcf_k2m<<<4096, 128, k2m_smem>>>(conv2_b);
    pcf_k3<<<dim3(64, 2, 7), 256>>>(fc1_w);
    pcf_k3r<<<512, 256>>>(fc1_b);
    pcf_k4<<<160, 256>>>(fc2_w, fc2_b, out);
}

// round 14
// speedup vs baseline: 3.5401x; 1.6188x over previous
#include <cuda_runtime.h>
#include <cuda_fp16.h>
#include <math.h>
#include <stdint.h>

typedef unsigned long long u64t;

// ---------------- packed fp32 (k3) ----------------
#define FMA2(d, a, b) asm("fma.rn.f32x2 %0, %1, %2, %0;" : "+l"(d) : "l"(a), "l"(b))
#define PACKF2(o, lo, hi) asm("mov.b64 %0, {%1, %2};" : "=l"(o) : "r"(__float_as_uint(lo)), "r"(__float_as_uint(hi)))

// ---------------- warp MMA helpers ----------------
#define LDMATRIX_X4(r0, r1, r2, r3, addr) \
    asm volatile("ldmatrix.sync.aligned.m8n8.x4.shared.b16 {%0,%1,%2,%3}, [%4];" \
                 : "=r"(r0), "=r"(r1), "=r"(r2), "=r"(r3) : "r"(addr))
#define MMA16816(c0, c1, c2, c3, a0, a1, a2, a3, b0, b1) \
    asm volatile("mma.sync.aligned.m16n8k16.row.col.f32.f16.f16.f32 " \
                 "{%0,%1,%2,%3}, {%4,%5,%6,%7}, {%8,%9}, {%0,%1,%2,%3};" \
                 : "+f"(c0), "+f"(c1), "+f"(c2), "+f"(c3) \
                 : "r"(a0), "r"(a1), "r"(a2), "r"(a3), "r"(b0), "r"(b1))

__device__ __forceinline__ uint32_t smem_u32(const void* p) {
    uint32_t a;
    asm("{ .reg .u64 t; cvta.to.shared.u64 t, %1; cvt.u32.u64 %0, t; }" : "=r"(a) : "l"(p));
    return a;
}

// ---------------- scratch ----------------
// conv1 out fp16, stride-40 HWC: [n][pos 16x16][40]: 0..15 gabor ci, 16 id, rest pad
__device__ __align__(16) __half g_s1h[4096 * 256 * 40];
__device__ float g_s2[4096 * 64 * 49];
__device__ float g_fc1[4096 * 128];
__device__ float g_fc1p[7][4096 * 128];
// B fragments: gabor [tap 0..8][ntile 0..7][lane][2], id at "tap 9"
__device__ uint32_t g_wpk[10 * 8 * 32 * 2];

// ---------------------------------------------------------------------------
// prep: mma B-fragments (m16n8k16 .col) of conv2 weights, fp16.
// gabor (tap<9): k axis = ci 0..15. id (tap==9): k axis = tap 0..8 (pad 16),
// weights = sum of the 16 identical identity input channels.
// lane l: k0=(l%4)*2, n=ntile*8+l/4; b0={k0,k0+1}, b1={k0+8,k0+9}.
// ---------------------------------------------------------------------------
__global__ void pcf_prep(const float* __restrict__ w2g)
{
    int idx = blockIdx.x * 256 + threadIdx.x;
    if (idx >= 2560) return;                  // 10*8*32
    int lane = idx & 31;
    int ntg  = (idx >> 5) & 7;
    int tap  = idx >> 8;                      // 0..9
    int n    = ntg * 8 + (lane >> 2);
    int k0   = (lane & 3) * 2;

    float v[4];
#pragma unroll
    for (int j = 0; j < 4; j++) {
        int k = k0 + (j & 1) + ((j >> 1) * 8);
        float w = 0.f;
        if (tap < 9) {
            w = w2g[n * 288 + k * 9 + tap];            // ci = k (0..15)
        } else if (k < 9) {
#pragma unroll
            for (int c = 16; c < 32; c++) w += w2g[n * 288 + c * 9 + k];
        }
        v[j] = w;
    }
    uint32_t u0 = (uint32_t)__half_as_ushort(__float2half(v[0])) |
                  ((uint32_t)__half_as_ushort(__float2half(v[1])) << 16);
    uint32_t u1 = (uint32_t)__half_as_ushort(__float2half(v[2])) |
                  ((uint32_t)__half_as_ushort(__float2half(v[3])) << 16);
    g_wpk[idx * 2]     = u0;
    g_wpk[idx * 2 + 1] = u1;
}

// ---------------------------------------------------------------------------
// k1: gabor conv (16 ch) + identity + relu + maxpool2 -> g_s1h (stride-40 HWC)
// ---------------------------------------------------------------------------
__global__ void __launch_bounds__(256) pcf_k1(
    const float* __restrict__ x, const float* __restrict__ theta,
    const float* __restrict__ sigma, const float* __restrict__ gamma_,
    const float* __restrict__ lambd, const float* __restrict__ psi)
{
    __shared__ float ps[30][30];
    __shared__ float gw[16][9];
    const int n = blockIdx.x, t = threadIdx.x;

    for (int idx = t; idx < 900; idx += 256) ((float*)ps)[idx] = 0.f;
    {   // zero the 20 KB image tile
        uint4* z = (uint4*)(g_s1h + (size_t)n * 10240);
        for (int idx = t; idx < 1280; idx += 256) z[idx] = make_uint4(0, 0, 0, 0);
    }
    __syncthreads();

    const float* xim = x + (size_t)n * 784;
    for (int idx = t; idx < 784; idx += 256) {
        int r = idx / 28, c = idx - r * 28;
        ps[r + 1][c + 1] = xim[idx];
    }
    if (t < 144) {
        int f = t / 9, k = t - f * 9;
        float xg = (float)(k / 3) - 1.f;
        float yg = (float)(k % 3) - 1.f;
        float th = theta[f];
        float cth = cosf(th), sth = sinf(th);
        float xt = xg * cth + yg * sth;
        float yt = -xg * sth + yg * cth;
        float sx = sigma[f];
        float sy = sigma[f] / gamma_[f];
        float env = expf(-0.5f * (xt * xt / (sx * sx) + yt * yt / (sy * sy)));
        float car = cosf(6.283185307179586f * xt / lambd[f] + psi[f]);
        gw[f][k] = env * car;
    }
    __syncthreads();

    __half* out1 = g_s1h + (size_t)n * 10240;

    if (t < 196) {   // identity channel at half-slot 16
        int i = t / 14, j = t - (t / 14) * 14;
        float m = fmaxf(fmaxf(ps[2 * i + 1][2 * j + 1], ps[2 * i + 1][2 * j + 2]),
                        fmaxf(ps[2 * i + 2][2 * j + 1], ps[2 * i + 2][2 * j + 2]));
        out1[((i + 1) * 16 + (j + 1)) * 40 + 16] = __float2half(fmaxf(m, 0.f));
    }

    for (int idx = t; idx < 16 * 196; idx += 256) {
        int c = idx / 196, p = idx - (idx / 196) * 196;
        int i = p / 14, j = p - (p / 14) * 14;
        float w[9];
#pragma unroll
        for (int k = 0; k < 9; k++) w[k] = gw[c][k];
        float m = -1e30f;
#pragma unroll
        for (int di = 0; di < 2; di++)
#pragma unroll
            for (int dj = 0; dj < 2; dj++) {
                float s = 0.f;
#pragma unroll
                for (int kh = 0; kh < 3; kh++)
#pragma unroll
                    for (int kw = 0; kw < 3; kw++)
                        s += ps[2 * i + di + kh][2 * j + dj + kw] * w[kh * 3 + kw];
                m = fmaxf(m, s);
            }
        out1[((i + 1) * 16 + (j + 1)) * 40 + c] = __float2half(fmaxf(m, 0.f));
    }
}

// ---------------------------------------------------------------------------
// k2m: conv2 via HMMA, conflict-free LDSM, K=16.
// 1 CTA/image, 256 thr = 8 warps: warp&3 -> channel group (16 ch),
// warp>>2 -> tile half. Tile = 4 quads of one quad-row (quad-rows padded to 8
// cols; col 7 dummy). m-row encoding: cj | ql<<1 | ci<<3 -> each ldmatrix
// phase covers 8 consecutive positions; stride 80 B -> pos*5 mod 8 distinct.
// Per tile: 9 gabor LDSM/MMA pairs (direct-tap) + 1 id LDSM/MMA (im2col
// halves 24..39, built once per image). Pool: fmax(c0,c2) + shfl.xor 4.
// ---------------------------------------------------------------------------
__global__ void __launch_bounds__(256) pcf_k2m(const float* __restrict__ b2)
{
    extern __shared__ char smraw[];
    float* sO = (float*)(smraw + 20480);     // [64][56]
    const int n = blockIdx.x, t = threadIdx.x;
    const int warp = t >> 5, lane = t & 31;
    const int wc = warp & 3, th = warp >> 2;

    // stage 20 KB image tile
    {
        const uint4* src = (const uint4*)(g_s1h + (size_t)n * 10240);
        uint4* dst = (uint4*)smraw;
        for (int i = t; i < 1280; i += 256) dst[i] = src[i];
    }
    __syncthreads();

    // build id im2col: halves 24+tap = id[pos + tapoffset]
    {
        __half* sh = (__half*)smraw;
        for (int idx = t; idx < 2304; idx += 256) {
            int pos = idx / 9, tap = idx - (idx / 9) * 9;
            int pi = (pos >> 4) + tap / 3 - 1;
            int pj = (pos & 15) + tap % 3 - 1;
            __half v = __ushort_as_half(0);
            if (pi >= 0 && pi < 16 && pj >= 0 && pj < 16)
                v = sh[(pi * 16 + pj) * 40 + 16];
            sh[pos * 40 + 24 + tap] = v;
        }
    }

    // B fragments: 9 gabor taps + id, 2 ntiles each
    uint32_t Bg[9][2][2], Bi[2][2];
#pragma unroll
    for (int tap = 0; tap < 9; tap++)
#pragma unroll
        for (int nt = 0; nt < 2; nt++) {
            uint2 v = ((const uint2*)g_wpk)[(tap * 8 + wc * 2 + nt) * 32 + lane];
            Bg[tap][nt][0] = v.x; Bg[tap][nt][1] = v.y;
        }
#pragma unroll
    for (int nt = 0; nt < 2; nt++) {
        uint2 v = ((const uint2*)g_wpk)[(72 + wc * 2 + nt) * 32 + lane];
        Bi[nt][0] = v.x; Bi[nt][1] = v.y;
    }
    __syncthreads();

    const uint32_t sb = smem_u32(smraw);

    for (int tt = 0; tt < 7; tt++) {
        const int tile = th * 7 + tt;
        const int qi = tile >> 1, qj0 = (tile & 1) * 4;

        // this lane's A-row -> position (m = cj | ql<<1 | ci<<3)
        const int r = lane & 15;
        const int ci = r >> 3, ql = (r >> 1) & 3, cj = r & 1;
        int qj = qj0 + ql; if (qj > 6) qj = 6;
        const int pi = 2 * qi + ci + 1, pj = 2 * qj + cj + 1;
        const uint32_t a_base = sb + (uint32_t)((pi * 16 + pj) * 80) + (uint32_t)(lane & 16);

        float acc[2][4];
#pragma unroll
        for (int nt = 0; nt < 2; nt++)
#pragma unroll
            for (int k = 0; k < 4; k++) acc[nt][k] = 0.f;

#pragma unroll
        for (int kh = 0; kh < 3; kh++)
#pragma unroll
            for (int kw = 0; kw < 3; kw++) {
                const int tap = kh * 3 + kw;
                const int shift = ((kh - 1) * 16 + (kw - 1)) * 80;
                uint32_t a0, a1, a2, a3;
                LDMATRIX_X4(a0, a1, a2, a3, a_base + shift);
                MMA16816(acc[0][0], acc[0][1], acc[0][2], acc[0][3],
                         a0, a1, a2, a3, Bg[tap][0][0], Bg[tap][0][1]);
                MMA16816(acc[1][0], acc[1][1], acc[1][2], acc[1][3],
                         a0, a1, a2, a3, Bg[tap][1][0], Bg[tap][1][1]);
            }
        {   // identity channel: K = 9 taps (im2col at byte offset 48)
            uint32_t a0, a1, a2, a3;
            LDMATRIX_X4(a0, a1, a2, a3, a_base + 48);
            MMA16816(acc[0][0], acc[0][1], acc[0][2], acc[0][3],
                     a0, a1, a2, a3, Bi[0][0], Bi[0][1]);
            MMA16816(acc[1][0], acc[1][1], acc[1][2], acc[1][3],
                     a0, a1, a2, a3, Bi[1][0], Bi[1][1]);
        }

        // pool: ci via c0<->c2 (same lane), cj via shfl.xor 4
        const int rd = lane >> 2;            // D row 0..7
        const bool wr = (rd & 1) == 0;
        const int qls = rd >> 1;             // quad slot 0..3
#pragma unroll
        for (int nt = 0; nt < 2; nt++)
#pragma unroll
            for (int k0 = 0; k0 < 2; k0++) {
                float v = fmaxf(acc[nt][k0], acc[nt][k0 + 2]);
                v = fmaxf(v, __shfl_xor_sync(0xffffffffu, v, 4));
                if (wr) {
                    int ch = wc * 16 + nt * 8 + (lane & 3) * 2 + k0;
                    sO[ch * 56 + qi * 8 + qj0 + qls] = v;
                }
            }
    }
    __syncthreads();

    // bias + relu + coalesced store (skip dummy quad col 7)
    float* outp = g_s2 + (size_t)n * 3136;
    for (int idx = t; idx < 3136; idx += 256) {
        int ch = idx / 49, p = idx - ch * 49;
        int qi = p / 7, qj = p - qi * 7;
        outp[idx] = fmaxf(sO[ch * 56 + qi * 8 + qj] + __ldg(b2 + ch), 0.f);
    }
}

// ---------------------------------------------------------------------------
// k3: fc1 partials, split-K x7 (unchanged, proven)
// ---------------------------------------------------------------------------
__global__ void __launch_bounds__(256) pcf_k3(const float* __restrict__ w1)
{
    __shared__ float As[32 * 64];
    __shared__ float Bs[32 * 64];
    const int t = threadIdx.x;
    const int tx = t & 15, ty = t >> 4;
    const int n0 = blockIdx.x * 64;
    const int m0 = blockIdx.y * 64;
    const int ks = blockIdx.z;

    u64t acc2[4][2];
#pragma unroll
    for (int u = 0; u < 4; u++) { acc2[u][0] = 0ull; acc2[u][1] = 0ull; }

    for (int kt = ks * 14; kt < ks * 14 + 14; kt++) {
#pragma unroll
        for (int s = 0; s < 8; s++) {
            int idx = t + s * 256;
            int k = idx & 31, row = idx >> 5;
            int phys = (((row >> 2) ^ (k & 15)) << 2) | (row & 3);
            As[k * 64 + phys] = g_s2[(size_t)(n0 + row) * 3136 + kt * 32 + k];
            Bs[k * 64 + phys] = w1[(size_t)(m0 + row) * 3136 + kt * 32 + k];
        }
        __syncthreads();
#pragma unroll
        for (int kk = 0; kk < 32; kk++) {
            float4 a4 = *(const float4*)(As + kk * 64 + ((ty ^ (kk & 15)) << 2));
            float4 b4 = *(const float4*)(Bs + kk * 64 + ((tx ^ (kk & 15)) << 2));
            u64t bp0, bp1;
            PACKF2(bp0, b4.x, b4.y);
            PACKF2(bp1, b4.z, b4.w);
            float av[4] = { a4.x, a4.y, a4.z, a4.w };
#pragma unroll
            for (int u = 0; u < 4; u++) {
                u64t ap;
                PACKF2(ap, av[u], av[u]);
                FMA2(acc2[u][0], bp0, ap);
                FMA2(acc2[u][1], bp1, ap);
            }
        }
        __syncthreads();
    }

    float* pout = g_fc1p[ks];
#pragma unroll
    for (int u = 0; u < 4; u++) {
        int nrow = n0 + ty * 4 + u;
#pragma unroll
        for (int p = 0; p < 2; p++) {
            union { u64t v; float2 f; } cv;
            cv.v = acc2[u][p];
            int mm = m0 + tx * 4 + p * 2;
            pout[(size_t)nrow * 128 + mm]     = cv.f.x;
            pout[(size_t)nrow * 128 + mm + 1] = cv.f.y;
        }
    }
}

__global__ void __launch_bounds__(256) pcf_k3r(const float* __restrict__ b1)
{
    int gid = blockIdx.x * 256 + threadIdx.x;
    int col4 = gid & 31;
    float4 s = ((const float4*)g_fc1p[0])[gid];
#pragma unroll
    for (int p = 1; p < 7; p++) {
        float4 v = ((const float4*)g_fc1p[p])[gid];
        s.x += v.x; s.y += v.y; s.z += v.z; s.w += v.w;
    }
    float4 b = ((const float4*)b1)[col4];
    s.x = fmaxf(s.x + b.x, 0.f);
    s.y = fmaxf(s.y + b.y, 0.f);
    s.z = fmaxf(s.z + b.z, 0.f);
    s.w = fmaxf(s.w + b.w, 0.f);
    ((float4*)g_fc1)[gid] = s;
}

__global__ void __launch_bounds__(256) pcf_k4(
    const float* __restrict__ w2, const float* __restrict__ b2,
    float* __restrict__ out)
{
    int gid = blockIdx.x * 256 + threadIdx.x;
    if (gid >= 4096 * 10) return;
    int nrow = gid / 10, o = gid - nrow * 10;
    const float4* a = (const float4*)(g_fc1 + (size_t)nrow * 128);
    const float4* w = (const float4*)(w2 + o * 128);
    float s = b2[o];
#pragma unroll
    for (int q = 0; q < 32; q++) {
        float4 av = a[q], wv = w[q];
        s += av.x * wv.x + av.y * wv.y + av.z * wv.z + av.w * wv.w;
    }
    out[gid] = s;
}

// ---------------------------------------------------------------------------
extern "C" void kernel_launch(void* const* d_in, const int* in_sizes, int n_in,
                              void* d_out, int out_size)
{
    const float* x       = (const float*)d_in[0];
    const float* theta   = (const float*)d_in[1];
    const float* sigma   = (const float*)d_in[2];
    const float* gamma_  = (const float*)d_in[3];
    const float* lambd   = (const float*)d_in[4];
    const float* psi     = (const float*)d_in[5];
    const float* conv2_w = (const float*)d_in[6];
    const float* conv2_b = (const float*)d_in[7];
    const float* fc1_w   = (const float*)d_in[8];
    const float* fc1_b   = (const float*)d_in[9];
    const float* fc2_w   = (const float*)d_in[10];
    const float* fc2_b   = (const float*)d_in[11];
    float* out = (float*)d_out;

    const int k2m_smem = 20480 + 64 * 56 * 4;   // 34816 bytes

    pcf_prep<<<10, 256>>>(conv2_w);
    pcf_k1<<<4096, 256>>>(x, theta, sigma, gamma_, lambd, psi);
    pcf_k2m<<<4096, 256, k2m_smem>>>(conv2_b);
    pcf_k3<<<dim3(64, 2, 7), 256>>>(fc1_w);
    pcf_k3r<<<512, 256>>>(fc1_b);
    pcf_k4<<<160, 256>>>(fc2_w, fc2_b, out);
}

// round 15
// speedup vs baseline: 4.4111x; 1.2460x over previous
#include <cuda_runtime.h>
#include <cuda_fp16.h>
#include <math.h>
#include <stdint.h>

typedef unsigned long long u64t;

// ---------------- warp MMA helpers ----------------
#define LDMATRIX_X4(r0, r1, r2, r3, addr) \
    asm volatile("ldmatrix.sync.aligned.m8n8.x4.shared.b16 {%0,%1,%2,%3}, [%4];" \
                 : "=r"(r0), "=r"(r1), "=r"(r2), "=r"(r3) : "r"(addr))
#define MMA16816(c0, c1, c2, c3, a0, a1, a2, a3, b0, b1) \
    asm volatile("mma.sync.aligned.m16n8k16.row.col.f32.f16.f16.f32 " \
                 "{%0,%1,%2,%3}, {%4,%5,%6,%7}, {%8,%9}, {%0,%1,%2,%3};" \
                 : "+f"(c0), "+f"(c1), "+f"(c2), "+f"(c3) \
                 : "r"(a0), "r"(a1), "r"(a2), "r"(a3), "r"(b0), "r"(b1))

__device__ __forceinline__ uint32_t smem_u32(const void* p) {
    uint32_t a;
    asm("{ .reg .u64 t; cvta.to.shared.u64 t, %1; cvt.u32.u64 %0, t; }" : "=r"(a) : "l"(p));
    return a;
}

// ---------------- scratch ----------------
__device__ __align__(16) __half g_s1h[4096 * 256 * 40];   // conv1 out, stride-40 HWC
__device__ __align__(16) __half g_s2h[4096 * 3136];       // conv2 out hi plane (fp16 split)
__device__ __align__(16) __half g_s2l[4096 * 3136];       // conv2 out lo plane
__device__ __align__(16) __half g_w1h[128 * 3136];        // fc1 weights hi plane
__device__ __align__(16) __half g_w1l[128 * 3136];        // fc1 weights lo plane
__device__ float g_fc1[4096 * 128];
__device__ float g_fc1p[7][4096 * 128];
__device__ uint32_t g_wpk[10 * 8 * 32 * 2];               // conv2 B fragments

// ---------------------------------------------------------------------------
// prep: conv2 mma B-fragments (unchanged from R14)
// ---------------------------------------------------------------------------
__global__ void pcf_prep(const float* __restrict__ w2g)
{
    int idx = blockIdx.x * 256 + threadIdx.x;
    if (idx >= 2560) return;
    int lane = idx & 31;
    int ntg  = (idx >> 5) & 7;
    int tap  = idx >> 8;
    int n    = ntg * 8 + (lane >> 2);
    int k0   = (lane & 3) * 2;

    float v[4];
#pragma unroll
    for (int j = 0; j < 4; j++) {
        int k = k0 + (j & 1) + ((j >> 1) * 8);
        float w = 0.f;
        if (tap < 9) {
            w = w2g[n * 288 + k * 9 + tap];
        } else if (k < 9) {
#pragma unroll
            for (int c = 16; c < 32; c++) w += w2g[n * 288 + c * 9 + k];
        }
        v[j] = w;
    }
    uint32_t u0 = (uint32_t)__half_as_ushort(__float2half(v[0])) |
                  ((uint32_t)__half_as_ushort(__float2half(v[1])) << 16);
    uint32_t u1 = (uint32_t)__half_as_ushort(__float2half(v[2])) |
                  ((uint32_t)__half_as_ushort(__float2half(v[3])) << 16);
    g_wpk[idx * 2]     = u0;
    g_wpk[idx * 2 + 1] = u1;
}

// ---------------------------------------------------------------------------
// prep3: split fc1 weights into fp16 hi/lo planes (row-major [128][3136])
// ---------------------------------------------------------------------------
__global__ void pcf_prep3(const float* __restrict__ w1)
{
    int idx = blockIdx.x * 256 + threadIdx.x;
    if (idx >= 128 * 3136) return;
    float v = w1[idx];
    __half h = __float2half(v);
    g_w1h[idx] = h;
    g_w1l[idx] = __float2half(v - __half2float(h));
}

// ---------------------------------------------------------------------------
// k1: gabor conv (16 ch) + identity + relu + maxpool2 -> g_s1h (unchanged)
// ---------------------------------------------------------------------------
__global__ void __launch_bounds__(256) pcf_k1(
    const float* __restrict__ x, const float* __restrict__ theta,
    const float* __restrict__ sigma, const float* __restrict__ gamma_,
    const float* __restrict__ lambd, const float* __restrict__ psi)
{
    __shared__ float ps[30][30];
    __shared__ float gw[16][9];
    const int n = blockIdx.x, t = threadIdx.x;

    for (int idx = t; idx < 900; idx += 256) ((float*)ps)[idx] = 0.f;
    {
        uint4* z = (uint4*)(g_s1h + (size_t)n * 10240);
        for (int idx = t; idx < 1280; idx += 256) z[idx] = make_uint4(0, 0, 0, 0);
    }
    __syncthreads();

    const float* xim = x + (size_t)n * 784;
    for (int idx = t; idx < 784; idx += 256) {
        int r = idx / 28, c = idx - r * 28;
        ps[r + 1][c + 1] = xim[idx];
    }
    if (t < 144) {
        int f = t / 9, k = t - f * 9;
        float xg = (float)(k / 3) - 1.f;
        float yg = (float)(k % 3) - 1.f;
        float th = theta[f];
        float cth = cosf(th), sth = sinf(th);
        float xt = xg * cth + yg * sth;
        float yt = -xg * sth + yg * cth;
        float sx = sigma[f];
        float sy = sigma[f] / gamma_[f];
        float env = expf(-0.5f * (xt * xt / (sx * sx) + yt * yt / (sy * sy)));
        float car = cosf(6.283185307179586f * xt / lambd[f] + psi[f]);
        gw[f][k] = env * car;
    }
    __syncthreads();

    __half* out1 = g_s1h + (size_t)n * 10240;

    if (t < 196) {
        int i = t / 14, j = t - (t / 14) * 14;
        float m = fmaxf(fmaxf(ps[2 * i + 1][2 * j + 1], ps[2 * i + 1][2 * j + 2]),
                        fmaxf(ps[2 * i + 2][2 * j + 1], ps[2 * i + 2][2 * j + 2]));
        out1[((i + 1) * 16 + (j + 1)) * 40 + 16] = __float2half(fmaxf(m, 0.f));
    }

    for (int idx = t; idx < 16 * 196; idx += 256) {
        int c = idx / 196, p = idx - (idx / 196) * 196;
        int i = p / 14, j = p - (p / 14) * 14;
        float w[9];
#pragma unroll
        for (int k = 0; k < 9; k++) w[k] = gw[c][k];
        float m = -1e30f;
#pragma unroll
        for (int di = 0; di < 2; di++)
#pragma unroll
            for (int dj = 0; dj < 2; dj++) {
                float s = 0.f;
#pragma unroll
                for (int kh = 0; kh < 3; kh++)
#pragma unroll
                    for (int kw = 0; kw < 3; kw++)
                        s += ps[2 * i + di + kh][2 * j + dj + kw] * w[kh * 3 + kw];
                m = fmaxf(m, s);
            }
        out1[((i + 1) * 16 + (j + 1)) * 40 + c] = __float2half(fmaxf(m, 0.f));
    }
}

// ---------------------------------------------------------------------------
// k2m: conv2 via HMMA (as R14), epilogue now writes fp16 hi/lo planes
// ---------------------------------------------------------------------------
__global__ void __launch_bounds__(256) pcf_k2m(const float* __restrict__ b2)
{
    extern __shared__ char smraw[];
    float* sO = (float*)(smraw + 20480);     // [64][56]
    const int n = blockIdx.x, t = threadIdx.x;
    const int warp = t >> 5, lane = t & 31;
    const int wc = warp & 3, th = warp >> 2;

    {
        const uint4* src = (const uint4*)(g_s1h + (size_t)n * 10240);
        uint4* dst = (uint4*)smraw;
        for (int i = t; i < 1280; i += 256) dst[i] = src[i];
    }
    __syncthreads();

    {   // id im2col into halves 24..32
        __half* sh = (__half*)smraw;
        for (int idx = t; idx < 2304; idx += 256) {
            int pos = idx / 9, tap = idx - (idx / 9) * 9;
            int pi = (pos >> 4) + tap / 3 - 1;
            int pj = (pos & 15) + tap % 3 - 1;
            __half v = __ushort_as_half(0);
            if (pi >= 0 && pi < 16 && pj >= 0 && pj < 16)
                v = sh[(pi * 16 + pj) * 40 + 16];
            sh[pos * 40 + 24 + tap] = v;
        }
    }

    uint32_t Bg[9][2][2], Bi[2][2];
#pragma unroll
    for (int tap = 0; tap < 9; tap++)
#pragma unroll
        for (int nt = 0; nt < 2; nt++) {
            uint2 v = ((const uint2*)g_wpk)[(tap * 8 + wc * 2 + nt) * 32 + lane];
            Bg[tap][nt][0] = v.x; Bg[tap][nt][1] = v.y;
        }
#pragma unroll
    for (int nt = 0; nt < 2; nt++) {
        uint2 v = ((const uint2*)g_wpk)[(72 + wc * 2 + nt) * 32 + lane];
        Bi[nt][0] = v.x; Bi[nt][1] = v.y;
    }
    __syncthreads();

    const uint32_t sb = smem_u32(smraw);

    for (int tt = 0; tt < 7; tt++) {
        const int tile = th * 7 + tt;
        const int qi = tile >> 1, qj0 = (tile & 1) * 4;

        const int r = lane & 15;
        const int ci = r >> 3, ql = (r >> 1) & 3, cj = r & 1;
        int qj = qj0 + ql; if (qj > 6) qj = 6;
        const int pi = 2 * qi + ci + 1, pj = 2 * qj + cj + 1;
        const uint32_t a_base = sb + (uint32_t)((pi * 16 + pj) * 80) + (uint32_t)(lane & 16);

        float acc[2][4];
#pragma unroll
        for (int nt = 0; nt < 2; nt++)
#pragma unroll
            for (int k = 0; k < 4; k++) acc[nt][k] = 0.f;

#pragma unroll
        for (int kh = 0; kh < 3; kh++)
#pragma unroll
            for (int kw = 0; kw < 3; kw++) {
                const int tap = kh * 3 + kw;
                const int shift = ((kh - 1) * 16 + (kw - 1)) * 80;
                uint32_t a0, a1, a2, a3;
                LDMATRIX_X4(a0, a1, a2, a3, a_base + shift);
                MMA16816(acc[0][0], acc[0][1], acc[0][2], acc[0][3],
                         a0, a1, a2, a3, Bg[tap][0][0], Bg[tap][0][1]);
                MMA16816(acc[1][0], acc[1][1], acc[1][2], acc[1][3],
                         a0, a1, a2, a3, Bg[tap][1][0], Bg[tap][1][1]);
            }
        {
            uint32_t a0, a1, a2, a3;
            LDMATRIX_X4(a0, a1, a2, a3, a_base + 48);
            MMA16816(acc[0][0], acc[0][1], acc[0][2], acc[0][3],
                     a0, a1, a2, a3, Bi[0][0], Bi[0][1]);
            MMA16816(acc[1][0], acc[1][1], acc[1][2], acc[1][3],
                     a0, a1, a2, a3, Bi[1][0], Bi[1][1]);
        }

        const int rd = lane >> 2;
        const bool wr = (rd & 1) == 0;
        const int qls = rd >> 1;
#pragma unroll
        for (int nt = 0; nt < 2; nt++)
#pragma unroll
            for (int k0 = 0; k0 < 2; k0++) {
                float v = fmaxf(acc[nt][k0], acc[nt][k0 + 2]);
                v = fmaxf(v, __shfl_xor_sync(0xffffffffu, v, 4));
                if (wr) {
                    int ch = wc * 16 + nt * 8 + (lane & 3) * 2 + k0;
                    sO[ch * 56 + qi * 8 + qj0 + qls] = v;
                }
            }
    }
    __syncthreads();

    // bias + relu -> fp16 hi/lo planes (fc1 HMMA input)
    for (int idx = t; idx < 3136; idx += 256) {
        int ch = idx / 49, p = idx - ch * 49;
        int qi = p / 7, qj = p - qi * 7;
        float v = fmaxf(sO[ch * 56 + qi * 8 + qj] + __ldg(b2 + ch), 0.f);
        __half h = __float2half(v);
        g_s2h[(size_t)n * 3136 + idx] = h;
        g_s2l[(size_t)n * 3136 + idx] = __float2half(v - __half2float(h));
    }
}

// ---------------------------------------------------------------------------
// k3h: fc1 GEMM via HMMA, fp16-split (Ah*Wh + Ah*Wl + Al*Wh), split-K x7.
// CTA = M64 x N128, grid (64, 7). 8 warps = (mw 0..3) x (nw 0..1), each warp
// M16 x N64. smem rows stride 40 halves (80 B, x5 mod 8 conflict-free).
// Partials -> g_fc1p[ks]; reduce in k3r (unchanged).
// ---------------------------------------------------------------------------
__global__ void __launch_bounds__(256) pcf_k3h()
{
    __shared__ __half sA[2][64 * 40];
    __shared__ __half sW[2][128 * 40];
    const int t = threadIdx.x, warp = t >> 5, lane = t & 31;
    const int mw = warp & 3, nw = warp >> 2;
    const int m0 = blockIdx.x * 64;
    const int ks = blockIdx.y;

    float acc[4][2][4];
#pragma unroll
    for (int nn = 0; nn < 4; nn++)
#pragma unroll
        for (int s = 0; s < 2; s++)
#pragma unroll
            for (int k = 0; k < 4; k++) acc[nn][s][k] = 0.f;

    const int arow = t >> 2, aseg = t & 3;
    const uint32_t sa0 = smem_u32(&sA[0][0]), sa1 = smem_u32(&sA[1][0]);
    const uint32_t sw0 = smem_u32(&sW[0][0]), sw1 = smem_u32(&sW[1][0]);

    // per-lane ldmatrix address offsets (bytes)
    const uint32_t a_off = (uint32_t)((mw * 16 + (lane & 15)) * 80) + (uint32_t)((lane >> 4) * 16);
    const uint32_t b_row = (uint32_t)(nw * 64 + (lane & 7) + (((lane >> 4) & 1) << 3));
    const uint32_t b_off = b_row * 80 + (uint32_t)(((lane >> 3) & 1) * 16);

    for (int c = 0; c < 14; c++) {
        const int k0 = ks * 448 + c * 32;
        {   // A chunk: 64 rows x 32 halves, both planes
            size_t ofs = (size_t)(m0 + arow) * 3136 + k0 + aseg * 8;
            *(uint4*)(&sA[0][arow * 40 + aseg * 8]) = *(const uint4*)(g_s2h + ofs);
            *(uint4*)(&sA[1][arow * 40 + aseg * 8]) = *(const uint4*)(g_s2l + ofs);
        }
#pragma unroll
        for (int u = 0; u < 2; u++) {   // W chunk: 128 rows x 32 halves
            int idx = t + u * 256;
            int row = idx >> 2, seg = idx & 3;
            size_t ofs = (size_t)row * 3136 + k0 + seg * 8;
            *(uint4*)(&sW[0][row * 40 + seg * 8]) = *(const uint4*)(g_w1h + ofs);
            *(uint4*)(&sW[1][row * 40 + seg * 8]) = *(const uint4*)(g_w1l + ofs);
        }
        __syncthreads();

#pragma unroll
        for (int k2 = 0; k2 < 2; k2++) {
            const uint32_t ka = (uint32_t)(k2 * 32);
            uint32_t ah0, ah1, ah2, ah3, al0, al1, al2, al3;
            LDMATRIX_X4(ah0, ah1, ah2, ah3, sa0 + a_off + ka);
            LDMATRIX_X4(al0, al1, al2, al3, sa1 + a_off + ka);
#pragma unroll
            for (int nn = 0; nn < 4; nn++) {
                const uint32_t wo = b_off + (uint32_t)(nn * 16 * 80) + ka;
                uint32_t bh0, bh1, bh2, bh3, bl0, bl1, bl2, bl3;
                LDMATRIX_X4(bh0, bh1, bh2, bh3, sw0 + wo);
                LDMATRIX_X4(bl0, bl1, bl2, bl3, sw1 + wo);
                MMA16816(acc[nn][0][0], acc[nn][0][1], acc[nn][0][2], acc[nn][0][3],
                         ah0, ah1, ah2, ah3, bh0, bh1);
                MMA16816(acc[nn][1][0], acc[nn][1][1], acc[nn][1][2], acc[nn][1][3],
                         ah0, ah1, ah2, ah3, bh2, bh3);
                MMA16816(acc[nn][0][0], acc[nn][0][1], acc[nn][0][2], acc[nn][0][3],
                         ah0, ah1, ah2, ah3, bl0, bl1);
                MMA16816(acc[nn][1][0], acc[nn][1][1], acc[nn][1][2], acc[nn][1][3],
                         ah0, ah1, ah2, ah3, bl2, bl3);
                MMA16816(acc[nn][0][0], acc[nn][0][1], acc[nn][0][2], acc[nn][0][3],
                         al0, al1, al2, al3, bh0, bh1);
                MMA16816(acc[nn][1][0], acc[nn][1][1], acc[nn][1][2], acc[nn][1][3],
                         al0, al1, al2, al3, bh2, bh3);
            }
        }
        __syncthreads();
    }

    // epilogue: write raw fp32 partials (c0,c1 -> row l/4; c2,c3 -> row l/4+8)
    float* pout = g_fc1p[ks];
    const int mrow = m0 + mw * 16 + (lane >> 2);
    const int nc0 = nw * 64 + (lane & 3) * 2;
#pragma unroll
    for (int nn = 0; nn < 4; nn++)
#pragma unroll
        for (int s = 0; s < 2; s++) {
            int ncol = nc0 + nn * 16 + s * 8;
            *(float2*)(&pout[(size_t)mrow * 128 + ncol]) =
                make_float2(acc[nn][s][0], acc[nn][s][1]);
            *(float2*)(&pout[(size_t)(mrow + 8) * 128 + ncol]) =
                make_float2(acc[nn][s][2], acc[nn][s][3]);
        }
}

// ---------------------------------------------------------------------------
// k3r: reduce 7 partials + bias + relu -> g_fc1 (unchanged)
// ---------------------------------------------------------------------------
__global__ void __launch_bounds__(256) pcf_k3r(const float* __restrict__ b1)
{
    int gid = blockIdx.x * 256 + threadIdx.x;
    int col4 = gid & 31;
    float4 s = ((const float4*)g_fc1p[0])[gid];
#pragma unroll
    for (int p = 1; p < 7; p++) {
        float4 v = ((const float4*)g_fc1p[p])[gid];
        s.x += v.x; s.y += v.y; s.z += v.z; s.w += v.w;
    }
    float4 b = ((const float4*)b1)[col4];
    s.x = fmaxf(s.x + b.x, 0.f);
    s.y = fmaxf(s.y + b.y, 0.f);
    s.z = fmaxf(s.z + b.z, 0.f);
    s.w = fmaxf(s.w + b.w, 0.f);
    ((float4*)g_fc1)[gid] = s;
}

__global__ void __launch_bounds__(256) pcf_k4(
    const float* __restrict__ w2, const float* __restrict__ b2,
    float* __restrict__ out)
{
    int gid = blockIdx.x * 256 + threadIdx.x;
    if (gid >= 4096 * 10) return;
    int nrow = gid / 10, o = gid - nrow * 10;
    const float4* a = (const float4*)(g_fc1 + (size_t)nrow * 128);
    const float4* w = (const float4*)(w2 + o * 128);
    float s = b2[o];
#pragma unroll
    for (int q = 0; q < 32; q++) {
        float4 av = a[q], wv = w[q];
        s += av.x * wv.x + av.y * wv.y + av.z * wv.z + av.w * wv.w;
    }
    out[gid] = s;
}

// ---------------------------------------------------------------------------
extern "C" void kernel_launch(void* const* d_in, const int* in_sizes, int n_in,
                              void* d_out, int out_size)
{
    const float* x       = (const float*)d_in[0];
    const float* theta   = (const float*)d_in[1];
    const float* sigma   = (const float*)d_in[2];
    const float* gamma_  = (const float*)d_in[3];
    const float* lambd   = (const float*)d_in[4];
    const float* psi     = (const float*)d_in[5];
    const float* conv2_w = (const float*)d_in[6];
    const float* conv2_b = (const float*)d_in[7];
    const float* fc1_w   = (const float*)d_in[8];
    const float* fc1_b   = (const float*)d_in[9];
    const float* fc2_w   = (const float*)d_in[10];
    const float* fc2_b   = (const float*)d_in[11];
    float* out = (float*)d_out;

    const int k2m_smem = 20480 + 64 * 56 * 4;   // 34816 bytes

    pcf_prep<<<10, 256>>>(conv2_w);
    pcf_prep3<<<1568, 256>>>(fc1_w);
    pcf_k1<<<4096, 256>>>(x, theta, sigma, gamma_, lambd, psi);
    pcf_k2m<<<4096, 256, k2m_smem>>>(conv2_b);
    pcf_k3h<<<dim3(64, 7), 256>>>();
    pcf_k3r<<<512, 256>>>(fc1_b);
    pcf_k4<<<160, 256>>>(fc2_w, fc2_b, out);
}